// round 14
// baseline (speedup 1.0000x reference)
#include <cuda_runtime.h>
#include <cuda_fp16.h>
#include <math.h>
#include <stdint.h>

namespace {
constexpr int B_ = 4, S_ = 1024, H_ = 16;
constexpr int M_ = B_ * S_;
constexpr float SC2 = 0.14396396f * 1.44269504f;    // 2/sqrt(193) * log2(e)
constexpr int KQS = 192, KVN = 576, KCT = 2080, VDIM = 136;
constexpr int NQA = 3712;                            // logical out width (3648 real)
constexpr int NQAW = 3840;                           // weight rows padded to 256-mult
constexpr size_t DSMEM_W = 2 * 30720;                // wide gemm: 2 stages x (A 10240 + B 20480)
// attn: 2 full K tiles (2x51200) + V hi/lo (2x34816) + t_k (512)
constexpr size_t DSMEM_F = 2 * 51200 + 2 * 34816 + 512;  // 172544
}

// fp32 scratch
__device__ float g_qkva[(size_t)M_ * NQA];
__device__ float g_kpe[(size_t)M_ * 64];
__device__ float g_kv2[(size_t)M_ * 4096];
__device__ float g_tq[(size_t)64 * S_], g_tk[(size_t)64 * S_];
__device__ float g_biasqa[NQA];
// fp16 projection operands
__device__ __half g_xh[(size_t)M_ * 2048];
__device__ __half g_wqkva[(size_t)NQAW * 2048];      // rows 3648..3839 stay 0
__device__ __half g_kvnh[(size_t)M_ * KVN];
__device__ __half g_wkvbh[(size_t)4096 * KVN];
__device__ __half g_ch[(size_t)M_ * KCT];            // cols 2064..2079 stay 0
__device__ __half g_woh[(size_t)2048 * KCT];
// fp16 attention operands (V natural token-major: [bh][s][136], dims 129..135 stay 0)
__device__ __half g_qsh[(size_t)64 * S_ * KQS];
__device__ __half g_ksh[(size_t)64 * S_ * KQS];
__device__ __half g_vth[(size_t)64 * S_ * VDIM], g_vtl[(size_t)64 * S_ * VDIM];

__device__ __forceinline__ uint32_t cvta_smem(const void* p) {
    uint32_t a;
    asm("{ .reg .u64 t; cvta.to.shared.u64 t, %1; cvt.u32.u64 %0, t; }" : "=r"(a) : "l"(p));
    return a;
}
#define CPASYNC16(s, g) asm volatile("cp.async.cg.shared.global [%0], [%1], 16;" :: "r"(s), "l"(g) : "memory")
#define CPCOMMIT()      asm volatile("cp.async.commit_group;" ::: "memory")
#define CPWAIT(n)       asm volatile("cp.async.wait_group %0;" :: "n"(n) : "memory")

__device__ __forceinline__ void ldsm_x4(uint32_t* r, uint32_t a) {
    asm volatile("ldmatrix.sync.aligned.m8n8.x4.shared.b16 {%0,%1,%2,%3}, [%4];"
                 : "=r"(r[0]), "=r"(r[1]), "=r"(r[2]), "=r"(r[3]) : "r"(a));
}
__device__ __forceinline__ void ldsm_x2(uint32_t* r, uint32_t a) {
    asm volatile("ldmatrix.sync.aligned.m8n8.x2.shared.b16 {%0,%1}, [%2];"
                 : "=r"(r[0]), "=r"(r[1]) : "r"(a));
}
__device__ __forceinline__ void ldsm_x2t(uint32_t* r, uint32_t a) {
    asm volatile("ldmatrix.sync.aligned.m8n8.x2.trans.shared.b16 {%0,%1}, [%2];"
                 : "=r"(r[0]), "=r"(r[1]) : "r"(a));
}
__device__ __forceinline__ void mma_f16(float* d, const uint32_t* a, const uint32_t* b) {
    asm volatile("mma.sync.aligned.m16n8k16.row.col.f32.f16.f16.f32 "
                 "{%0,%1,%2,%3}, {%4,%5,%6,%7}, {%8,%9}, {%0,%1,%2,%3};"
                 : "+f"(d[0]), "+f"(d[1]), "+f"(d[2]), "+f"(d[3])
                 : "r"(a[0]), "r"(a[1]), "r"(a[2]), "r"(a[3]), "r"(b[0]), "r"(b[1]));
}
__device__ __forceinline__ uint32_t packh2(float x, float y) {
    __half2 h = __floats2half2_rn(x, y);
    return *reinterpret_cast<uint32_t*>(&h);
}
__device__ __forceinline__ float warp_sum(float v) {
#pragma unroll
    for (int o = 16; o; o >>= 1) v += __shfl_xor_sync(0xffffffffu, v, o);
    return v;
}
__device__ __forceinline__ float block_sum_256(float v, float* sh) {
    int tid = threadIdx.x;
#pragma unroll
    for (int o = 16; o; o >>= 1) v += __shfl_xor_sync(0xffffffffu, v, o);
    __syncthreads();
    if ((tid & 31) == 0) sh[tid >> 5] = v;
    __syncthreads();
    if (tid < 32) {
        float t = (tid < 8) ? sh[tid] : 0.f;
#pragma unroll
        for (int o = 4; o; o >>= 1) t += __shfl_xor_sync(0xffffffffu, t, o);
        if (tid == 0) sh[0] = t;
    }
    __syncthreads();
    return sh[0];
}
__device__ __forceinline__ void hsplit(float v, __half* hi, __half* lo, long long i) {
    __half h = __float2half_rn(v);
    hi[i] = h;
    lo[i] = __float2half_rn(v - __half2float(h));
}
__device__ __forceinline__ uint2 pack4(float4 v) {
    __half2 a = __floats2half2_rn(v.x, v.y);
    __half2 b = __floats2half2_rn(v.z, v.w);
    uint2 o;
    o.x = *reinterpret_cast<uint32_t*>(&a);
    o.y = *reinterpret_cast<uint32_t*>(&b);
    return o;
}

// ====== wide fp16 GEMM: CTA 128x256, warp 64x64, BK=32 ======
__global__ void __launch_bounds__(256, 1)
gemm_h1w(const __half* __restrict__ A, int lda,
         const __half* __restrict__ Bm, int ldb,
         float* __restrict__ C, int ldc,
         const float* __restrict__ bias, int Nreal, int K)
{
    const int bm = blockIdx.y * 128, bn = blockIdx.x * 256;
    const int nch = K >> 5;
    extern __shared__ __align__(16) char smem[];
    const uint32_t sbase = cvta_smem(smem);
    const int tid = threadIdx.x, wid = tid >> 5, lane = tid & 31;
    const int wm = (wid >> 2) * 64, wn = (wid & 3) * 64;

    float acc[4][8][4] = {};

    auto load_stage = [&](int s, int c) {
        const long long k0 = (long long)c * 32;
        const uint32_t base = sbase + (uint32_t)s * 30720u;
#pragma unroll
        for (int j = 0; j < 2; ++j) {           // A: 128 rows x 4 segs
            const int cid = tid + j * 256;
            const int row = cid >> 2, ch = cid & 3;
            CPASYNC16(base + (uint32_t)(row * 80 + ch * 16),
                      A + (long long)(bm + row) * lda + k0 + ch * 8);
        }
#pragma unroll
        for (int j = 0; j < 4; ++j) {           // B: 256 rows x 4 segs
            const int cid = tid + j * 256;
            const int row = cid >> 2, ch = cid & 3;
            CPASYNC16(base + 10240u + (uint32_t)(row * 80 + ch * 16),
                      Bm + (long long)(bn + row) * ldb + k0 + ch * 8);
        }
        CPCOMMIT();
    };

    load_stage(0, 0);
    for (int c = 0; c < nch; ++c) {
        if (c + 1 < nch) { load_stage((c + 1) & 1, c + 1); CPWAIT(1); }
        else             { CPWAIT(0); }
        __syncthreads();
        const uint32_t st = sbase + (uint32_t)(c & 1) * 30720u;
#pragma unroll
        for (int ks = 0; ks < 2; ++ks) {
            uint32_t ah[4][4], bh[8][2];
            const int arow = wm + (lane & 15);
            const int acol = ks * 16 + (lane >> 4) * 8;
#pragma unroll
            for (int mf = 0; mf < 4; ++mf)
                ldsm_x4(ah[mf], st + (uint32_t)((arow + mf * 16) * 80 + acol * 2));
            const int brow = wn + (lane & 7);
            const int bcol = ks * 16 + ((lane >> 3) & 1) * 8;
#pragma unroll
            for (int nf = 0; nf < 8; ++nf)
                ldsm_x2(bh[nf], st + 10240u + (uint32_t)((brow + nf * 8) * 80 + bcol * 2));
#pragma unroll
            for (int mf = 0; mf < 4; ++mf)
#pragma unroll
                for (int nf = 0; nf < 8; ++nf)
                    mma_f16(acc[mf][nf], ah[mf], bh[nf]);
        }
        __syncthreads();
    }
#pragma unroll
    for (int mf = 0; mf < 4; ++mf) {
        const long long r0 = bm + wm + mf * 16 + (lane >> 2);
#pragma unroll
        for (int nf = 0; nf < 8; ++nf) {
            const int col = bn + wn + nf * 8 + (lane & 3) * 2;
            const float b0 = bias ? bias[min(col, Nreal - 1)] : 0.f;
            const float b1 = bias ? bias[min(col + 1, Nreal - 1)] : 0.f;
            if (col < Nreal) {
                C[r0 * ldc + col] = acc[mf][nf][0] + b0;
                C[(r0 + 8) * ldc + col] = acc[mf][nf][2] + b0;
            }
            if (col + 1 < Nreal) {
                C[r0 * ldc + col + 1] = acc[mf][nf][1] + b1;
                C[(r0 + 8) * ldc + col + 1] = acc[mf][nf][3] + b1;
            }
        }
    }
}

// ============ fused flash-attention + Lorentz centroid ============
__global__ void __launch_bounds__(256, 1)
fused_attn(const __half* __restrict__ qsh, const __half* __restrict__ ksh,
           const float* __restrict__ tqg, const float* __restrict__ tkg,
           const __half* __restrict__ vh, const __half* __restrict__ vl,
           __half* __restrict__ ch)
{
    const int iq = 7 - (int)blockIdx.x;
    const int bh = (int)blockIdx.y;
    const long long qkbase = (long long)bh * S_ * KQS;
    const long long vgbase = (long long)bh * S_ * VDIM;
    extern __shared__ __align__(16) char smem[];
    const uint32_t sbase = cvta_smem(smem);
    const uint32_t vsH = sbase + 102400u, vsL = vsH + 34816u;
    float* tks = (float*)(smem + 102400u + 2 * 34816u);
    const int tid = threadIdx.x, w = tid >> 5, lane = tid & 31;

    const __half* qh_g = qsh + qkbase + (long long)iq * 128 * KQS;
    const float tq0 = tqg[(long long)bh * S_ + iq * 128 + w * 16 + (lane >> 2)];
    const float tq1 = tqg[(long long)bh * S_ + iq * 128 + w * 16 + (lane >> 2) + 8];

    auto load_tile192 = [&](uint32_t dst, const __half* src) {
#pragma unroll
        for (int t2 = 0; t2 < 12; ++t2) {
            const int idx = tid + t2 * 256;
            const int row = idx / 24, seg = idx % 24;
            CPASYNC16(dst + (uint32_t)(row * 400 + seg * 16),
                      src + (long long)row * KQS + seg * 8);
        }
        CPCOMMIT();
    };
    auto load_vtile = [&](int j) {
        for (int idx = tid; idx < 2176; idx += 256) {
            const int row = idx / 17, seg = idx % 17;
            const long long g = vgbase + (long long)(j * 128 + row) * VDIM + seg * 8;
            CPASYNC16(vsH + (uint32_t)(row * 272 + seg * 16), vh + g);
            CPASYNC16(vsL + (uint32_t)(row * 272 + seg * 16), vl + g);
        }
        CPCOMMIT();
    };

    uint32_t qf[12][4];
    {
        load_tile192(sbase, qh_g);
        CPWAIT(0);
        __syncthreads();
#pragma unroll
        for (int kk = 0; kk < 12; ++kk) {
            const uint32_t aoff =
                (uint32_t)((w * 16 + (lane & 15)) * 400 + (kk * 16 + (lane >> 4) * 8) * 2);
            ldsm_x4(qf[kk], sbase + aoff);
        }
        __syncthreads();
    }

    float O[17][4] = {};
    float m0 = -1e30f, m1 = -1e30f, l0 = 0.f, l1 = 0.f;

    load_tile192(sbase, ksh + qkbase);
    load_vtile(0);

    for (int j = 0; j <= iq; ++j) {
        const uint32_t kst = sbase + (uint32_t)(j & 1) * 51200u;
        const int jn = min(j + 1, iq);
        if (tid < 128) tks[tid] = tkg[(long long)bh * S_ + j * 128 + tid];
        load_tile192(sbase + (uint32_t)(jn & 1) * 51200u,
                     ksh + qkbase + (long long)jn * 128 * KQS);
        CPWAIT(2);
        __syncthreads();

        float acc[16][4] = {};
#pragma unroll
        for (int kc = 0; kc < 12; ++kc) {
#pragma unroll
            for (int nf = 0; nf < 16; ++nf) {
                const uint32_t boff =
                    (uint32_t)((nf * 8 + (lane & 7)) * 400 +
                               (kc * 16 + ((lane >> 3) & 1) * 8) * 2);
                uint32_t kk[2];
                ldsm_x2(kk, kst + boff);
                mma_f16(acc[nf], qf[kc], kk);
            }
        }
        {
            const int c0b = (lane & 3) * 2;
#pragma unroll
            for (int nf = 0; nf < 16; ++nf) {
                const float k0v = tks[nf * 8 + c0b], k1v = tks[nf * 8 + c0b + 1];
                acc[nf][0] -= tq0 * k0v; acc[nf][1] -= tq0 * k1v;
                acc[nf][2] -= tq1 * k0v; acc[nf][3] -= tq1 * k1v;
            }
        }
        if (j == iq) {
            const int rt0 = w * 16 + (lane >> 2), rt1 = rt0 + 8;
#pragma unroll
            for (int nf = 0; nf < 16; ++nf) {
                const int ct = nf * 8 + (lane & 3) * 2;
                if (ct > rt0)     acc[nf][0] = -1e30f;
                if (ct + 1 > rt0) acc[nf][1] = -1e30f;
                if (ct > rt1)     acc[nf][2] = -1e30f;
                if (ct + 1 > rt1) acc[nf][3] = -1e30f;
            }
        }
        float mx0 = -1e30f, mx1 = -1e30f;
#pragma unroll
        for (int nf = 0; nf < 16; ++nf) {
            mx0 = fmaxf(mx0, fmaxf(acc[nf][0], acc[nf][1]));
            mx1 = fmaxf(mx1, fmaxf(acc[nf][2], acc[nf][3]));
        }
        mx0 = fmaxf(mx0, __shfl_xor_sync(~0u, mx0, 1));
        mx0 = fmaxf(mx0, __shfl_xor_sync(~0u, mx0, 2));
        mx1 = fmaxf(mx1, __shfl_xor_sync(~0u, mx1, 1));
        mx1 = fmaxf(mx1, __shfl_xor_sync(~0u, mx1, 2));
        const float mn0 = fmaxf(m0, mx0), mn1 = fmaxf(m1, mx1);
        const float a0 = exp2f((m0 - mn0) * SC2), a1 = exp2f((m1 - mn1) * SC2);
        l0 *= a0; l1 *= a1;
#pragma unroll
        for (int nf = 0; nf < 17; ++nf) {
            O[nf][0] *= a0; O[nf][1] *= a0; O[nf][2] *= a1; O[nf][3] *= a1;
        }
        float s0 = 0.f, s1 = 0.f;
#pragma unroll
        for (int nf = 0; nf < 16; ++nf) {
            acc[nf][0] = exp2f((acc[nf][0] - mn0) * SC2);
            acc[nf][1] = exp2f((acc[nf][1] - mn0) * SC2);
            acc[nf][2] = exp2f((acc[nf][2] - mn1) * SC2);
            acc[nf][3] = exp2f((acc[nf][3] - mn1) * SC2);
            s0 += acc[nf][0] + acc[nf][1];
            s1 += acc[nf][2] + acc[nf][3];
        }
        s0 += __shfl_xor_sync(~0u, s0, 1); s0 += __shfl_xor_sync(~0u, s0, 2);
        s1 += __shfl_xor_sync(~0u, s1, 1); s1 += __shfl_xor_sync(~0u, s1, 2);
        l0 += s0; l1 += s1; m0 = mn0; m1 = mn1;

        CPWAIT(1);
        __syncthreads();
#pragma unroll
        for (int kf = 0; kf < 8; ++kf) {
            uint32_t Ph[4];
            Ph[0] = packh2(acc[2 * kf][0], acc[2 * kf][1]);
            Ph[1] = packh2(acc[2 * kf][2], acc[2 * kf][3]);
            Ph[2] = packh2(acc[2 * kf + 1][0], acc[2 * kf + 1][1]);
            Ph[3] = packh2(acc[2 * kf + 1][2], acc[2 * kf + 1][3]);
            const uint32_t vrow = (uint32_t)((kf * 16 + (lane & 15)) * 272);
#pragma unroll
            for (int nf = 0; nf < 17; ++nf) {
                uint32_t vh2[2], vl2[2];
                ldsm_x2t(vh2, vsH + vrow + (uint32_t)(nf * 16));
                ldsm_x2t(vl2, vsL + vrow + (uint32_t)(nf * 16));
                mma_f16(O[nf], Ph, vh2);
                mma_f16(O[nf], Ph, vl2);
            }
        }
        __syncthreads();
        load_vtile(jn);
    }
    const float i0 = 1.f / l0, i1 = 1.f / l1;
    float ss0 = 0.f, ss1 = 0.f;
#pragma unroll
    for (int nf = 0; nf < 17; ++nf) {
        O[nf][0] *= i0; O[nf][1] *= i0; O[nf][2] *= i1; O[nf][3] *= i1;
        ss0 += O[nf][0] * O[nf][0] + O[nf][1] * O[nf][1];
        ss1 += O[nf][2] * O[nf][2] + O[nf][3] * O[nf][3];
    }
    ss0 += __shfl_xor_sync(~0u, ss0, 1); ss0 += __shfl_xor_sync(~0u, ss0, 2);
    ss1 += __shfl_xor_sync(~0u, ss1, 1); ss1 += __shfl_xor_sync(~0u, ss1, 2);
    const float t0 = __shfl_sync(~0u, O[0][0], lane & ~3);
    const float t1 = __shfl_sync(~0u, O[0][2], lane & ~3);
    const float d0 = rsqrtf(fmaxf(fabsf(2.f * t0 * t0 - ss0), 1e-8f));
    const float d1 = rsqrtf(fmaxf(fabsf(2.f * t1 * t1 - ss1), 1e-8f));
    const int hh = bh & 15;
    const long long tok0 = (long long)(bh >> 4) * 1024 + iq * 128 + w * 16 + (lane >> 2);
    const long long o0 = tok0 * KCT + hh * 129, o1 = (tok0 + 8) * KCT + hh * 129;
#pragma unroll
    for (int nf = 0; nf < 17; ++nf) {
        const int cc = nf * 8 + (lane & 3) * 2;
        if (cc < 129) {
            ch[o0 + cc] = __float2half_rn(O[nf][0] * d0);
            ch[o1 + cc] = __float2half_rn(O[nf][2] * d1);
        }
        if (cc + 1 < 129) {
            ch[o0 + cc + 1] = __float2half_rn(O[nf][1] * d0);
            ch[o1 + cc + 1] = __float2half_rn(O[nf][3] * d1);
        }
    }
}

// ---------- elementwise (vectorized) ----------
__global__ void __launch_bounds__(256)
convert_h4_1d(const float4* __restrict__ src, uint2* __restrict__ dst, int n4)
{
    const int i = blockIdx.x * 256 + threadIdx.x;
    if (i < n4) dst[i] = pack4(src[i]);
}

__global__ void __launch_bounds__(256)
convert_h4_2d(const float* __restrict__ src, int lds,
              __half* __restrict__ dst, int ldd, int cols)
{
    const int r = blockIdx.y;
    const int c4 = blockIdx.x * 256 + threadIdx.x;
    const int cols4 = cols >> 2;
    if (c4 < cols4) {
        const float* p = src + (long long)r * lds + c4 * 4;
        float4 v;
        v.x = p[0]; v.y = p[1]; v.z = p[2]; v.w = p[3];
        *(uint2*)(dst + (long long)r * ldd + c4 * 4) = pack4(v);
    } else if (c4 < cols4 + (cols & 3)) {
        const int c = cols4 * 4 + (c4 - cols4);
        dst[(long long)r * ldd + c] = __float2half_rn(src[(long long)r * lds + c]);
    }
}

__global__ void __launch_bounds__(256)
biascat_kernel(const float* __restrict__ a, const float* __restrict__ b,
               float* __restrict__ dst)
{
    const int i = blockIdx.x * 256 + threadIdx.x;
    if (i >= NQA) return;
    if (i < 3072) dst[i] = a[i];
    else if (i < 3648) dst[i] = b[i - 3072];
    else dst[i] = 0.f;
}

__global__ void __launch_bounds__(256)
rmsnorm_kpe_kernel(const float* __restrict__ qkva, const float* __restrict__ w,
                   const float* __restrict__ fc, const float* __restrict__ fs,
                   __half* __restrict__ kvnh, float* __restrict__ kpe)
{
    const int tok = blockIdx.x, s = tok & (S_ - 1), tid = threadIdx.x;
    const float* in = qkva + (size_t)tok * NQA + 3072;
    __shared__ float sp[512];
    __shared__ float sh[8];
    float local = 0.f;
    for (int i = tid; i < 512; i += 256) { float v = in[i]; local += v * v; }
    float r = rsqrtf(block_sum_256(local, sh) * (1.0f / 512.f) + 1e-6f);
    float l2 = 0.f;
    for (int i = tid; i < 512; i += 256) {
        float v = in[i] * r * w[i];
        sp[i] = v;
        l2 += v * v;
    }
    float tot2 = block_sum_256(l2, sh);
    const long long ob = (long long)tok * KVN;
    if (tid == 0) kvnh[ob] = __float2half_rn(sqrtf(tot2 + 1.f));
    for (int i = tid; i < 512; i += 256) kvnh[ob + 1 + i] = __float2half_rn(sp[i]);
    if (tid < 32) {
        float x1 = in[512 + 2 * tid], x2 = in[512 + 2 * tid + 1];
        float c = fc[s * 32 + tid], sn = fs[s * 32 + tid];
        kpe[(size_t)tok * 64 + 2 * tid]     = x1 * c - x2 * sn;
        kpe[(size_t)tok * 64 + 2 * tid + 1] = x1 * sn + x2 * c;
    }
}

__global__ void __launch_bounds__(256)
post_q_kernel(const float* __restrict__ qkva, const float* __restrict__ fc,
              const float* __restrict__ fs,
              __half* __restrict__ qshp, float* __restrict__ tq)
{
    const int gw = (blockIdx.x * blockDim.x + threadIdx.x) >> 5, lane = threadIdx.x & 31;
    if (gw >= M_ * H_) return;
    const int h = gw % H_, tok = gw / H_, b = tok / S_, s = tok & (S_ - 1);
    const float* qr = qkva + (size_t)tok * NQA + h * 192;
    const float4 qv = *(const float4*)(qr + lane * 4);
    const float c = fc[s * 32 + lane], sn = fs[s * 32 + lane];
    const float x1 = qr[128 + 2 * lane], x2 = qr[128 + 2 * lane + 1];
    const float r0 = x1 * c - x2 * sn, r1 = x1 * sn + x2 * c;
    float ss = r0 * r0 + r1 * r1 + qv.x * qv.x + qv.y * qv.y + qv.z * qv.z + qv.w * qv.w;
    ss = warp_sum(ss);
    const long long row = ((long long)b * H_ + h) * S_ + s;
    if (lane == 0) tq[row] = sqrtf(ss + 1.f);
    const long long ob = row * KQS;
    *(uint2*)(qshp + ob + lane * 4) = pack4(qv);
    *(__half2*)(qshp + ob + 128 + 2 * lane) = __floats2half2_rn(r0, r1);
}

__global__ void __launch_bounds__(256)
post_kv_kernel(const float* __restrict__ kv2, const float* __restrict__ kpe,
               __half* __restrict__ kshp, float* __restrict__ tk,
               __half* __restrict__ vhp, __half* __restrict__ vlp)
{
    const int gw = (blockIdx.x * blockDim.x + threadIdx.x) >> 5, lane = threadIdx.x & 31;
    if (gw >= M_ * H_) return;
    const int h = gw % H_, tok = gw / H_, b = tok / S_, s = tok & (S_ - 1);
    const float* row = kv2 + ((size_t)tok * H_ + h) * 256;
    const float* pe = kpe + (size_t)tok * 64;
    const float4 kn = *(const float4*)(row + lane * 4);
    const float2 pp = *(const float2*)(pe + lane * 2);
    float ss = kn.x * kn.x + kn.y * kn.y + kn.z * kn.z + kn.w * kn.w + pp.x * pp.x + pp.y * pp.y;
    ss = warp_sum(ss);
    const long long krow = ((long long)b * H_ + h) * S_ + s;
    if (lane == 0) tk[krow] = sqrtf(ss + 1.f);
    const long long kb = krow * KQS;
    *(uint2*)(kshp + kb + lane * 4) = pack4(kn);
    *(__half2*)(kshp + kb + 128 + 2 * lane) = __floats2half2_rn(pp.x, pp.y);
    const float4 vv = *(const float4*)(row + 128 + lane * 4);
    float sv = vv.x * vv.x + vv.y * vv.y + vv.z * vv.z + vv.w * vv.w;
    sv = warp_sum(sv);
    const long long vb = ((long long)b * H_ + h) * S_ * VDIM + (long long)s * VDIM;
    if (lane == 0) hsplit(sqrtf(sv + 1.f), vhp, vlp, vb);
    hsplit(vv.x, vhp, vlp, vb + 1 + lane * 4);
    hsplit(vv.y, vhp, vlp, vb + 2 + lane * 4);
    hsplit(vv.z, vhp, vlp, vb + 3 + lane * 4);
    hsplit(vv.w, vhp, vlp, vb + 4 + lane * 4);
}

__global__ void __launch_bounds__(256)
final_t_kernel(float* __restrict__ out)
{
    const int row = blockIdx.x, tid = threadIdx.x;
    float* p = out + (size_t)row * 2048;
    __shared__ float sh[8];
    float local = 0.f;
    for (int i = 1 + tid; i < 2048; i += 256) { float v = p[i]; local += v * v; }
    float tot = block_sum_256(local, sh);
    if (tid == 0) p[0] = sqrtf(tot + 1.f);
}

extern "C" void kernel_launch(void* const* d_in, const int* in_sizes, int n_in,
                              void* d_out, int out_size)
{
    (void)in_sizes; (void)n_in; (void)out_size;
    const float* x      = (const float*)d_in[0];
    const float* fc     = (const float*)d_in[1];
    const float* fs     = (const float*)d_in[2];
    const float* wq_w   = (const float*)d_in[4];
    const float* wq_b   = (const float*)d_in[5];
    const float* wkva_w = (const float*)d_in[6];
    const float* wkva_b = (const float*)d_in[7];
    const float* kvnw   = (const float*)d_in[8];
    const float* wkvb_w = (const float*)d_in[9];
    const float* wkvb_b = (const float*)d_in[10];
    const float* wo_w   = (const float*)d_in[11];
    const float* wo_b   = (const float*)d_in[12];
    float* out = (float*)d_out;

    float *qkva, *kpe, *kv2, *tq, *tk, *biasqa;
    cudaGetSymbolAddress((void**)&qkva, g_qkva);
    cudaGetSymbolAddress((void**)&kpe, g_kpe);
    cudaGetSymbolAddress((void**)&kv2, g_kv2);
    cudaGetSymbolAddress((void**)&tq, g_tq);
    cudaGetSymbolAddress((void**)&tk, g_tk);
    cudaGetSymbolAddress((void**)&biasqa, g_biasqa);
    __half *xh, *wqkva, *kvnh, *wkvbh, *ch, *woh, *qsh, *ksh, *vth, *vtl;
    cudaGetSymbolAddress((void**)&xh, g_xh);
    cudaGetSymbolAddress((void**)&wqkva, g_wqkva);
    cudaGetSymbolAddress((void**)&kvnh, g_kvnh);
    cudaGetSymbolAddress((void**)&wkvbh, g_wkvbh);
    cudaGetSymbolAddress((void**)&ch, g_ch);
    cudaGetSymbolAddress((void**)&woh, g_woh);
    cudaGetSymbolAddress((void**)&qsh, g_qsh);
    cudaGetSymbolAddress((void**)&ksh, g_ksh);
    cudaGetSymbolAddress((void**)&vth, g_vth);
    cudaGetSymbolAddress((void**)&vtl, g_vtl);

    cudaFuncSetAttribute(gemm_h1w, cudaFuncAttributeMaxDynamicSharedMemorySize, (int)DSMEM_W);
    cudaFuncSetAttribute(fused_attn, cudaFuncAttributeMaxDynamicSharedMemorySize, (int)DSMEM_F);

    const dim3 blk(256);
    convert_h4_1d<<<(M_ * 2048 / 4 + 255) / 256, blk>>>(
        (const float4*)x, (uint2*)xh, M_ * 2048 / 4);
    convert_h4_1d<<<(3072 * 2048 / 4 + 255) / 256, blk>>>(
        (const float4*)wq_w, (uint2*)wqkva, 3072 * 2048 / 4);
    convert_h4_1d<<<(576 * 2048 / 4 + 255) / 256, blk>>>(
        (const float4*)wkva_w, (uint2*)(wqkva + (size_t)3072 * 2048), 576 * 2048 / 4);
    convert_h4_2d<<<dim3(1, 4096), blk>>>(wkvb_w, 513, wkvbh, KVN, 513);
    convert_h4_2d<<<dim3(3, 2047), blk>>>(wo_w, 2064, woh, KCT, 2064);
    biascat_kernel<<<15, blk>>>(wq_b, wkva_b, biasqa);

    // fused Q + KV-A projection: (4096x2048) @ (3840x2048)^T, 15x32 CTAs
    gemm_h1w<<<dim3(15, 32), blk, DSMEM_W>>>(xh, 2048, wqkva, 2048,
                                             qkva, NQA, biasqa, 3648, 2048);
    rmsnorm_kpe_kernel<<<M_, blk>>>(qkva, kvnw, fc, fs, kvnh, kpe);
    // KV-B proj: (4096x576) @ (4096x576)^T, 16x32 CTAs
    gemm_h1w<<<dim3(16, 32), blk, DSMEM_W>>>(kvnh, KVN, wkvbh, KVN,
                                             kv2, 4096, wkvb_b, 4096, KVN);
    post_q_kernel<<<(M_ * H_) / 8, blk>>>(qkva, fc, fs, qsh, tq);
    post_kv_kernel<<<(M_ * H_) / 8, blk>>>(kv2, kpe, ksh, tk, vth, vtl);
    fused_attn<<<dim3(8, 64), blk, DSMEM_F>>>(qsh, ksh, tq, tk, vth, vtl, ch);
    // out proj: (4096x2080) @ (2047x2080)^T, 8x32 CTAs
    gemm_h1w<<<dim3(8, 32), blk, DSMEM_W>>>(ch, KCT, woh, KCT,
                                            out + 1, 2048, wo_b, 2047, KCT);
    final_t_kernel<<<M_, blk>>>(out);
}

// round 15
// speedup vs baseline: 1.2010x; 1.2010x over previous
#include <cuda_runtime.h>
#include <cuda_fp16.h>
#include <math.h>
#include <stdint.h>

namespace {
constexpr int B_ = 4, S_ = 1024, H_ = 16;
constexpr int M_ = B_ * S_;
constexpr float SC2 = 0.14396396f * 1.44269504f;    // 2/sqrt(193) * log2(e)
constexpr int KQS = 192, KVN = 576, KCT = 2112, VDIM = 136;
constexpr int NQA = 3712;                            // 3072 (q) + 576 (kva) + 64 pad
constexpr size_t DSMEM_H = 2 * 2 * 18432;            // gemm: 2 stages x (A+B), BK=64, pitch 144
// attn: 2 full K tiles (2x51200) + V hi/lo (2x34816) + t_k (512)
constexpr size_t DSMEM_F = 2 * 51200 + 2 * 34816 + 512;  // 172544
}

// fp32 scratch
__device__ float g_qkva[(size_t)M_ * NQA];
__device__ float g_kpe[(size_t)M_ * 64];
__device__ float g_kv2[(size_t)M_ * 4096];
__device__ float g_tq[(size_t)64 * S_], g_tk[(size_t)64 * S_];
__device__ float g_biasqa[NQA];
// fp16 projection operands
__device__ __half g_xh[(size_t)M_ * 2048];
__device__ __half g_wqkva[(size_t)NQA * 2048];       // rows 3648..3711 stay 0
__device__ __half g_kvnh[(size_t)M_ * KVN];
__device__ __half g_wkvbh[(size_t)4096 * KVN];
__device__ __half g_ch[(size_t)M_ * KCT];            // cols 2064..2111 stay 0
__device__ __half g_woh[(size_t)2048 * KCT];
// fp16 attention operands (V natural token-major: [bh][s][136], dims 129..135 stay 0)
__device__ __half g_qsh[(size_t)64 * S_ * KQS];
__device__ __half g_ksh[(size_t)64 * S_ * KQS];
__device__ __half g_vth[(size_t)64 * S_ * VDIM], g_vtl[(size_t)64 * S_ * VDIM];

__device__ __forceinline__ uint32_t cvta_smem(const void* p) {
    uint32_t a;
    asm("{ .reg .u64 t; cvta.to.shared.u64 t, %1; cvt.u32.u64 %0, t; }" : "=r"(a) : "l"(p));
    return a;
}
#define CPASYNC16(s, g) asm volatile("cp.async.cg.shared.global [%0], [%1], 16;" :: "r"(s), "l"(g) : "memory")
#define CPCOMMIT()      asm volatile("cp.async.commit_group;" ::: "memory")
#define CPWAIT(n)       asm volatile("cp.async.wait_group %0;" :: "n"(n) : "memory")

__device__ __forceinline__ void ldsm_x4(uint32_t* r, uint32_t a) {
    asm volatile("ldmatrix.sync.aligned.m8n8.x4.shared.b16 {%0,%1,%2,%3}, [%4];"
                 : "=r"(r[0]), "=r"(r[1]), "=r"(r[2]), "=r"(r[3]) : "r"(a));
}
__device__ __forceinline__ void ldsm_x2(uint32_t* r, uint32_t a) {
    asm volatile("ldmatrix.sync.aligned.m8n8.x2.shared.b16 {%0,%1}, [%2];"
                 : "=r"(r[0]), "=r"(r[1]) : "r"(a));
}
__device__ __forceinline__ void ldsm_x2t(uint32_t* r, uint32_t a) {
    asm volatile("ldmatrix.sync.aligned.m8n8.x2.trans.shared.b16 {%0,%1}, [%2];"
                 : "=r"(r[0]), "=r"(r[1]) : "r"(a));
}
__device__ __forceinline__ void mma_f16(float* d, const uint32_t* a, const uint32_t* b) {
    asm volatile("mma.sync.aligned.m16n8k16.row.col.f32.f16.f16.f32 "
                 "{%0,%1,%2,%3}, {%4,%5,%6,%7}, {%8,%9}, {%0,%1,%2,%3};"
                 : "+f"(d[0]), "+f"(d[1]), "+f"(d[2]), "+f"(d[3])
                 : "r"(a[0]), "r"(a[1]), "r"(a[2]), "r"(a[3]), "r"(b[0]), "r"(b[1]));
}
__device__ __forceinline__ uint32_t packh2(float x, float y) {
    __half2 h = __floats2half2_rn(x, y);
    return *reinterpret_cast<uint32_t*>(&h);
}
__device__ __forceinline__ float warp_sum(float v) {
#pragma unroll
    for (int o = 16; o; o >>= 1) v += __shfl_xor_sync(0xffffffffu, v, o);
    return v;
}
__device__ __forceinline__ float block_sum_256(float v, float* sh) {
    int tid = threadIdx.x;
#pragma unroll
    for (int o = 16; o; o >>= 1) v += __shfl_xor_sync(0xffffffffu, v, o);
    __syncthreads();
    if ((tid & 31) == 0) sh[tid >> 5] = v;
    __syncthreads();
    if (tid < 32) {
        float t = (tid < 8) ? sh[tid] : 0.f;
#pragma unroll
        for (int o = 4; o; o >>= 1) t += __shfl_xor_sync(0xffffffffu, t, o);
        if (tid == 0) sh[0] = t;
    }
    __syncthreads();
    return sh[0];
}
__device__ __forceinline__ void hsplit(float v, __half* hi, __half* lo, long long i) {
    __half h = __float2half_rn(v);
    hi[i] = h;
    lo[i] = __float2half_rn(v - __half2float(h));
}
__device__ __forceinline__ uint2 pack4(float4 v) {
    __half2 a = __floats2half2_rn(v.x, v.y);
    __half2 b = __floats2half2_rn(v.z, v.w);
    uint2 o;
    o.x = *reinterpret_cast<uint32_t*>(&a);
    o.y = *reinterpret_cast<uint32_t*>(&b);
    return o;
}

// ====== fp16 GEMM: CTA 128x128, warp 64x32, BK=64 (pitch 144B), 2 CTAs/SM ======
__global__ void __launch_bounds__(256, 2)
gemm_h1(const __half* __restrict__ A, int lda,
        const __half* __restrict__ Bm, int ldb,
        float* __restrict__ C, int ldc,
        const float* __restrict__ bias, int Nreal, int K)
{
    const int bm = blockIdx.y * 128, bn = blockIdx.x * 128;
    const int nch = K >> 6;
    extern __shared__ __align__(16) char smem[];
    const uint32_t sbase = cvta_smem(smem);
    const int tid = threadIdx.x, wid = tid >> 5, lane = tid & 31;
    const int wm = (wid >> 2) * 64, wn = (wid & 3) * 32;

    float acc[4][4][4] = {};
    const __half* srcs[2] = {A, Bm};

    auto load_stage = [&](int s, int c) {
        const long long k0 = (long long)c * 64;
#pragma unroll
        for (int arr = 0; arr < 2; ++arr) {
            const __half* src = srcs[arr];
            const int ld = (arr == 0) ? lda : ldb;
            const int ro = (arr == 0) ? bm : bn;
            const uint32_t base = sbase + (uint32_t)s * 36864u + (uint32_t)arr * 18432u;
#pragma unroll
            for (int j = 0; j < 4; ++j) {
                const int cid = tid + j * 256;   // 0..1023: 128 rows x 8 segs
                const int row = cid >> 3, ch = cid & 7;
                CPASYNC16(base + (uint32_t)(row * 144 + ch * 16),
                          src + (long long)(ro + row) * ld + k0 + ch * 8);
            }
        }
        CPCOMMIT();
    };

    load_stage(0, 0);
    for (int c = 0; c < nch; ++c) {
        if (c + 1 < nch) { load_stage((c + 1) & 1, c + 1); CPWAIT(1); }
        else             { CPWAIT(0); }
        __syncthreads();
        const uint32_t st = sbase + (uint32_t)(c & 1) * 36864u;
#pragma unroll
        for (int ks = 0; ks < 4; ++ks) {
            uint32_t ah[4][4], bh[4][2];
            const int arow = wm + (lane & 15);
            const int acol = ks * 16 + (lane >> 4) * 8;
#pragma unroll
            for (int mf = 0; mf < 4; ++mf)
                ldsm_x4(ah[mf], st + (uint32_t)((arow + mf * 16) * 144 + acol * 2));
            const int brow = wn + (lane & 7);
            const int bcol = ks * 16 + ((lane >> 3) & 1) * 8;
#pragma unroll
            for (int nf = 0; nf < 4; ++nf)
                ldsm_x2(bh[nf], st + 18432u + (uint32_t)((brow + nf * 8) * 144 + bcol * 2));
#pragma unroll
            for (int mf = 0; mf < 4; ++mf)
#pragma unroll
                for (int nf = 0; nf < 4; ++nf)
                    mma_f16(acc[mf][nf], ah[mf], bh[nf]);
        }
        __syncthreads();
    }
#pragma unroll
    for (int mf = 0; mf < 4; ++mf) {
        const long long r0 = bm + wm + mf * 16 + (lane >> 2);
#pragma unroll
        for (int nf = 0; nf < 4; ++nf) {
            const int col = bn + wn + nf * 8 + (lane & 3) * 2;
            const float b0 = bias ? bias[min(col, Nreal - 1)] : 0.f;
            const float b1 = bias ? bias[min(col + 1, Nreal - 1)] : 0.f;
            if (col < Nreal) {
                C[r0 * ldc + col] = acc[mf][nf][0] + b0;
                C[(r0 + 8) * ldc + col] = acc[mf][nf][2] + b0;
            }
            if (col + 1 < Nreal) {
                C[r0 * ldc + col + 1] = acc[mf][nf][1] + b1;
                C[(r0 + 8) * ldc + col + 1] = acc[mf][nf][3] + b1;
            }
        }
    }
}

// ============ fused flash-attention + Lorentz centroid (R13-proven) ============
__global__ void __launch_bounds__(256, 1)
fused_attn(const __half* __restrict__ qsh, const __half* __restrict__ ksh,
           const float* __restrict__ tqg, const float* __restrict__ tkg,
           const __half* __restrict__ vh, const __half* __restrict__ vl,
           __half* __restrict__ ch)
{
    const int iq = 7 - (int)blockIdx.x;
    const int bh = (int)blockIdx.y;
    const long long qkbase = (long long)bh * S_ * KQS;
    const long long vgbase = (long long)bh * S_ * VDIM;
    extern __shared__ __align__(16) char smem[];
    const uint32_t sbase = cvta_smem(smem);
    const uint32_t vsH = sbase + 102400u, vsL = vsH + 34816u;
    float* tks = (float*)(smem + 102400u + 2 * 34816u);
    const int tid = threadIdx.x, w = tid >> 5, lane = tid & 31;

    const __half* qh_g = qsh + qkbase + (long long)iq * 128 * KQS;
    const float tq0 = tqg[(long long)bh * S_ + iq * 128 + w * 16 + (lane >> 2)];
    const float tq1 = tqg[(long long)bh * S_ + iq * 128 + w * 16 + (lane >> 2) + 8];

    auto load_tile192 = [&](uint32_t dst, const __half* src) {
#pragma unroll
        for (int t2 = 0; t2 < 12; ++t2) {
            const int idx = tid + t2 * 256;
            const int row = idx / 24, seg = idx % 24;
            CPASYNC16(dst + (uint32_t)(row * 400 + seg * 16),
                      src + (long long)row * KQS + seg * 8);
        }
        CPCOMMIT();
    };
    auto load_vtile = [&](int j) {
        for (int idx = tid; idx < 2176; idx += 256) {
            const int row = idx / 17, seg = idx % 17;
            const long long g = vgbase + (long long)(j * 128 + row) * VDIM + seg * 8;
            CPASYNC16(vsH + (uint32_t)(row * 272 + seg * 16), vh + g);
            CPASYNC16(vsL + (uint32_t)(row * 272 + seg * 16), vl + g);
        }
        CPCOMMIT();
    };

    uint32_t qf[12][4];
    {
        load_tile192(sbase, qh_g);
        CPWAIT(0);
        __syncthreads();
#pragma unroll
        for (int kk = 0; kk < 12; ++kk) {
            const uint32_t aoff =
                (uint32_t)((w * 16 + (lane & 15)) * 400 + (kk * 16 + (lane >> 4) * 8) * 2);
            ldsm_x4(qf[kk], sbase + aoff);
        }
        __syncthreads();
    }

    float O[17][4] = {};
    float m0 = -1e30f, m1 = -1e30f, l0 = 0.f, l1 = 0.f;

    load_tile192(sbase, ksh + qkbase);
    load_vtile(0);

    for (int j = 0; j <= iq; ++j) {
        const uint32_t kst = sbase + (uint32_t)(j & 1) * 51200u;
        const int jn = min(j + 1, iq);
        if (tid < 128) tks[tid] = tkg[(long long)bh * S_ + j * 128 + tid];
        load_tile192(sbase + (uint32_t)(jn & 1) * 51200u,
                     ksh + qkbase + (long long)jn * 128 * KQS);
        CPWAIT(2);
        __syncthreads();

        float acc[16][4] = {};
#pragma unroll
        for (int kc = 0; kc < 12; ++kc) {
#pragma unroll
            for (int nf = 0; nf < 16; ++nf) {
                const uint32_t boff =
                    (uint32_t)((nf * 8 + (lane & 7)) * 400 +
                               (kc * 16 + ((lane >> 3) & 1) * 8) * 2);
                uint32_t kk[2];
                ldsm_x2(kk, kst + boff);
                mma_f16(acc[nf], qf[kc], kk);
            }
        }
        {
            const int c0b = (lane & 3) * 2;
#pragma unroll
            for (int nf = 0; nf < 16; ++nf) {
                const float k0v = tks[nf * 8 + c0b], k1v = tks[nf * 8 + c0b + 1];
                acc[nf][0] -= tq0 * k0v; acc[nf][1] -= tq0 * k1v;
                acc[nf][2] -= tq1 * k0v; acc[nf][3] -= tq1 * k1v;
            }
        }
        if (j == iq) {
            const int rt0 = w * 16 + (lane >> 2), rt1 = rt0 + 8;
#pragma unroll
            for (int nf = 0; nf < 16; ++nf) {
                const int ct = nf * 8 + (lane & 3) * 2;
                if (ct > rt0)     acc[nf][0] = -1e30f;
                if (ct + 1 > rt0) acc[nf][1] = -1e30f;
                if (ct > rt1)     acc[nf][2] = -1e30f;
                if (ct + 1 > rt1) acc[nf][3] = -1e30f;
            }
        }
        float mx0 = -1e30f, mx1 = -1e30f;
#pragma unroll
        for (int nf = 0; nf < 16; ++nf) {
            mx0 = fmaxf(mx0, fmaxf(acc[nf][0], acc[nf][1]));
            mx1 = fmaxf(mx1, fmaxf(acc[nf][2], acc[nf][3]));
        }
        mx0 = fmaxf(mx0, __shfl_xor_sync(~0u, mx0, 1));
        mx0 = fmaxf(mx0, __shfl_xor_sync(~0u, mx0, 2));
        mx1 = fmaxf(mx1, __shfl_xor_sync(~0u, mx1, 1));
        mx1 = fmaxf(mx1, __shfl_xor_sync(~0u, mx1, 2));
        const float mn0 = fmaxf(m0, mx0), mn1 = fmaxf(m1, mx1);
        const float a0 = exp2f((m0 - mn0) * SC2), a1 = exp2f((m1 - mn1) * SC2);
        l0 *= a0; l1 *= a1;
#pragma unroll
        for (int nf = 0; nf < 17; ++nf) {
            O[nf][0] *= a0; O[nf][1] *= a0; O[nf][2] *= a1; O[nf][3] *= a1;
        }
        float s0 = 0.f, s1 = 0.f;
#pragma unroll
        for (int nf = 0; nf < 16; ++nf) {
            acc[nf][0] = exp2f((acc[nf][0] - mn0) * SC2);
            acc[nf][1] = exp2f((acc[nf][1] - mn0) * SC2);
            acc[nf][2] = exp2f((acc[nf][2] - mn1) * SC2);
            acc[nf][3] = exp2f((acc[nf][3] - mn1) * SC2);
            s0 += acc[nf][0] + acc[nf][1];
            s1 += acc[nf][2] + acc[nf][3];
        }
        s0 += __shfl_xor_sync(~0u, s0, 1); s0 += __shfl_xor_sync(~0u, s0, 2);
        s1 += __shfl_xor_sync(~0u, s1, 1); s1 += __shfl_xor_sync(~0u, s1, 2);
        l0 += s0; l1 += s1; m0 = mn0; m1 = mn1;

        CPWAIT(1);
        __syncthreads();
#pragma unroll
        for (int kf = 0; kf < 8; ++kf) {
            uint32_t Ph[4];
            Ph[0] = packh2(acc[2 * kf][0], acc[2 * kf][1]);
            Ph[1] = packh2(acc[2 * kf][2], acc[2 * kf][3]);
            Ph[2] = packh2(acc[2 * kf + 1][0], acc[2 * kf + 1][1]);
            Ph[3] = packh2(acc[2 * kf + 1][2], acc[2 * kf + 1][3]);
            const uint32_t vrow = (uint32_t)((kf * 16 + (lane & 15)) * 272);
#pragma unroll
            for (int nf = 0; nf < 17; ++nf) {
                uint32_t vh2[2], vl2[2];
                ldsm_x2t(vh2, vsH + vrow + (uint32_t)(nf * 16));
                ldsm_x2t(vl2, vsL + vrow + (uint32_t)(nf * 16));
                mma_f16(O[nf], Ph, vh2);
                mma_f16(O[nf], Ph, vl2);
            }
        }
        __syncthreads();
        load_vtile(jn);
    }
    const float i0 = 1.f / l0, i1 = 1.f / l1;
    float ss0 = 0.f, ss1 = 0.f;
#pragma unroll
    for (int nf = 0; nf < 17; ++nf) {
        O[nf][0] *= i0; O[nf][1] *= i0; O[nf][2] *= i1; O[nf][3] *= i1;
        ss0 += O[nf][0] * O[nf][0] + O[nf][1] * O[nf][1];
        ss1 += O[nf][2] * O[nf][2] + O[nf][3] * O[nf][3];
    }
    ss0 += __shfl_xor_sync(~0u, ss0, 1); ss0 += __shfl_xor_sync(~0u, ss0, 2);
    ss1 += __shfl_xor_sync(~0u, ss1, 1); ss1 += __shfl_xor_sync(~0u, ss1, 2);
    const float t0 = __shfl_sync(~0u, O[0][0], lane & ~3);
    const float t1 = __shfl_sync(~0u, O[0][2], lane & ~3);
    const float d0 = rsqrtf(fmaxf(fabsf(2.f * t0 * t0 - ss0), 1e-8f));
    const float d1 = rsqrtf(fmaxf(fabsf(2.f * t1 * t1 - ss1), 1e-8f));
    const int hh = bh & 15;
    const long long tok0 = (long long)(bh >> 4) * 1024 + iq * 128 + w * 16 + (lane >> 2);
    const long long o0 = tok0 * KCT + hh * 129, o1 = (tok0 + 8) * KCT + hh * 129;
#pragma unroll
    for (int nf = 0; nf < 17; ++nf) {
        const int cc = nf * 8 + (lane & 3) * 2;
        if (cc < 129) {
            ch[o0 + cc] = __float2half_rn(O[nf][0] * d0);
            ch[o1 + cc] = __float2half_rn(O[nf][2] * d1);
        }
        if (cc + 1 < 129) {
            ch[o0 + cc + 1] = __float2half_rn(O[nf][1] * d0);
            ch[o1 + cc + 1] = __float2half_rn(O[nf][3] * d1);
        }
    }
}

// ---------- elementwise (vectorized) ----------
__global__ void __launch_bounds__(256)
convert_h4_1d(const float4* __restrict__ src, uint2* __restrict__ dst, int n4)
{
    const int i = blockIdx.x * 256 + threadIdx.x;
    if (i < n4) dst[i] = pack4(src[i]);
}

__global__ void __launch_bounds__(256)
convert_h4_2d(const float* __restrict__ src, int lds,
              __half* __restrict__ dst, int ldd, int cols)
{
    const int r = blockIdx.y;
    const int c4 = blockIdx.x * 256 + threadIdx.x;
    const int cols4 = cols >> 2;
    if (c4 < cols4) {
        const float* p = src + (long long)r * lds + c4 * 4;
        float4 v;
        v.x = p[0]; v.y = p[1]; v.z = p[2]; v.w = p[3];
        *(uint2*)(dst + (long long)r * ldd + c4 * 4) = pack4(v);
    } else if (c4 < cols4 + (cols & 3)) {
        const int c = cols4 * 4 + (c4 - cols4);
        dst[(long long)r * ldd + c] = __float2half_rn(src[(long long)r * lds + c]);
    }
}

__global__ void __launch_bounds__(256)
biascat_kernel(const float* __restrict__ a, const float* __restrict__ b,
               float* __restrict__ dst)
{
    const int i = blockIdx.x * 256 + threadIdx.x;
    if (i >= NQA) return;
    if (i < 3072) dst[i] = a[i];
    else if (i < 3648) dst[i] = b[i - 3072];
    else dst[i] = 0.f;
}

__global__ void __launch_bounds__(256)
rmsnorm_kpe_kernel(const float* __restrict__ qkva, const float* __restrict__ w,
                   const float* __restrict__ fc, const float* __restrict__ fs,
                   __half* __restrict__ kvnh, float* __restrict__ kpe)
{
    const int tok = blockIdx.x, s = tok & (S_ - 1), tid = threadIdx.x;
    const float* in = qkva + (size_t)tok * NQA + 3072;
    __shared__ float sp[512];
    __shared__ float sh[8];
    float local = 0.f;
    for (int i = tid; i < 512; i += 256) { float v = in[i]; local += v * v; }
    float r = rsqrtf(block_sum_256(local, sh) * (1.0f / 512.f) + 1e-6f);
    float l2 = 0.f;
    for (int i = tid; i < 512; i += 256) {
        float v = in[i] * r * w[i];
        sp[i] = v;
        l2 += v * v;
    }
    float tot2 = block_sum_256(l2, sh);
    const long long ob = (long long)tok * KVN;
    if (tid == 0) kvnh[ob] = __float2half_rn(sqrtf(tot2 + 1.f));
    for (int i = tid; i < 512; i += 256) kvnh[ob + 1 + i] = __float2half_rn(sp[i]);
    if (tid < 32) {
        float x1 = in[512 + 2 * tid], x2 = in[512 + 2 * tid + 1];
        float c = fc[s * 32 + tid], sn = fs[s * 32 + tid];
        kpe[(size_t)tok * 64 + 2 * tid]     = x1 * c - x2 * sn;
        kpe[(size_t)tok * 64 + 2 * tid + 1] = x1 * sn + x2 * c;
    }
}

__global__ void __launch_bounds__(256)
post_q_kernel(const float* __restrict__ qkva, const float* __restrict__ fc,
              const float* __restrict__ fs,
              __half* __restrict__ qshp, float* __restrict__ tq)
{
    const int gw = (blockIdx.x * blockDim.x + threadIdx.x) >> 5, lane = threadIdx.x & 31;
    if (gw >= M_ * H_) return;
    const int h = gw % H_, tok = gw / H_, b = tok / S_, s = tok & (S_ - 1);
    const float* qr = qkva + (size_t)tok * NQA + h * 192;
    const float4 qv = *(const float4*)(qr + lane * 4);
    const float c = fc[s * 32 + lane], sn = fs[s * 32 + lane];
    const float x1 = qr[128 + 2 * lane], x2 = qr[128 + 2 * lane + 1];
    const float r0 = x1 * c - x2 * sn, r1 = x1 * sn + x2 * c;
    float ss = r0 * r0 + r1 * r1 + qv.x * qv.x + qv.y * qv.y + qv.z * qv.z + qv.w * qv.w;
    ss = warp_sum(ss);
    const long long row = ((long long)b * H_ + h) * S_ + s;
    if (lane == 0) tq[row] = sqrtf(ss + 1.f);
    const long long ob = row * KQS;
    *(uint2*)(qshp + ob + lane * 4) = pack4(qv);
    *(__half2*)(qshp + ob + 128 + 2 * lane) = __floats2half2_rn(r0, r1);
}

__global__ void __launch_bounds__(256)
post_kv_kernel(const float* __restrict__ kv2, const float* __restrict__ kpe,
               __half* __restrict__ kshp, float* __restrict__ tk,
               __half* __restrict__ vhp, __half* __restrict__ vlp)
{
    const int gw = (blockIdx.x * blockDim.x + threadIdx.x) >> 5, lane = threadIdx.x & 31;
    if (gw >= M_ * H_) return;
    const int h = gw % H_, tok = gw / H_, b = tok / S_, s = tok & (S_ - 1);
    const float* row = kv2 + ((size_t)tok * H_ + h) * 256;
    const float* pe = kpe + (size_t)tok * 64;
    const float4 kn = *(const float4*)(row + lane * 4);
    const float2 pp = *(const float2*)(pe + lane * 2);
    float ss = kn.x * kn.x + kn.y * kn.y + kn.z * kn.z + kn.w * kn.w + pp.x * pp.x + pp.y * pp.y;
    ss = warp_sum(ss);
    const long long krow = ((long long)b * H_ + h) * S_ + s;
    if (lane == 0) tk[krow] = sqrtf(ss + 1.f);
    const long long kb = krow * KQS;
    *(uint2*)(kshp + kb + lane * 4) = pack4(kn);
    *(__half2*)(kshp + kb + 128 + 2 * lane) = __floats2half2_rn(pp.x, pp.y);
    const float4 vv = *(const float4*)(row + 128 + lane * 4);
    float sv = vv.x * vv.x + vv.y * vv.y + vv.z * vv.z + vv.w * vv.w;
    sv = warp_sum(sv);
    const long long vb = ((long long)b * H_ + h) * S_ * VDIM + (long long)s * VDIM;
    if (lane == 0) hsplit(sqrtf(sv + 1.f), vhp, vlp, vb);
    hsplit(vv.x, vhp, vlp, vb + 1 + lane * 4);
    hsplit(vv.y, vhp, vlp, vb + 2 + lane * 4);
    hsplit(vv.z, vhp, vlp, vb + 3 + lane * 4);
    hsplit(vv.w, vhp, vlp, vb + 4 + lane * 4);
}

__global__ void __launch_bounds__(256)
final_t_kernel(float* __restrict__ out)
{
    const int row = blockIdx.x, tid = threadIdx.x;
    float* p = out + (size_t)row * 2048;
    __shared__ float sh[8];
    float local = 0.f;
    for (int i = 1 + tid; i < 2048; i += 256) { float v = p[i]; local += v * v; }
    float tot = block_sum_256(local, sh);
    if (tid == 0) p[0] = sqrtf(tot + 1.f);
}

extern "C" void kernel_launch(void* const* d_in, const int* in_sizes, int n_in,
                              void* d_out, int out_size)
{
    (void)in_sizes; (void)n_in; (void)out_size;
    const float* x      = (const float*)d_in[0];
    const float* fc     = (const float*)d_in[1];
    const float* fs     = (const float*)d_in[2];
    const float* wq_w   = (const float*)d_in[4];
    const float* wq_b   = (const float*)d_in[5];
    const float* wkva_w = (const float*)d_in[6];
    const float* wkva_b = (const float*)d_in[7];
    const float* kvnw   = (const float*)d_in[8];
    const float* wkvb_w = (const float*)d_in[9];
    const float* wkvb_b = (const float*)d_in[10];
    const float* wo_w   = (const float*)d_in[11];
    const float* wo_b   = (const float*)d_in[12];
    float* out = (float*)d_out;

    float *qkva, *kpe, *kv2, *tq, *tk, *biasqa;
    cudaGetSymbolAddress((void**)&qkva, g_qkva);
    cudaGetSymbolAddress((void**)&kpe, g_kpe);
    cudaGetSymbolAddress((void**)&kv2, g_kv2);
    cudaGetSymbolAddress((void**)&tq, g_tq);
    cudaGetSymbolAddress((void**)&tk, g_tk);
    cudaGetSymbolAddress((void**)&biasqa, g_biasqa);
    __half *xh, *wqkva, *kvnh, *wkvbh, *ch, *woh, *qsh, *ksh, *vth, *vtl;
    cudaGetSymbolAddress((void**)&xh, g_xh);
    cudaGetSymbolAddress((void**)&wqkva, g_wqkva);
    cudaGetSymbolAddress((void**)&kvnh, g_kvnh);
    cudaGetSymbolAddress((void**)&wkvbh, g_wkvbh);
    cudaGetSymbolAddress((void**)&ch, g_ch);
    cudaGetSymbolAddress((void**)&woh, g_woh);
    cudaGetSymbolAddress((void**)&qsh, g_qsh);
    cudaGetSymbolAddress((void**)&ksh, g_ksh);
    cudaGetSymbolAddress((void**)&vth, g_vth);
    cudaGetSymbolAddress((void**)&vtl, g_vtl);

    cudaFuncSetAttribute(gemm_h1, cudaFuncAttributeMaxDynamicSharedMemorySize, (int)DSMEM_H);
    cudaFuncSetAttribute(fused_attn, cudaFuncAttributeMaxDynamicSharedMemorySize, (int)DSMEM_F);

    const dim3 blk(256);
    convert_h4_1d<<<(M_ * 2048 / 4 + 255) / 256, blk>>>(
        (const float4*)x, (uint2*)xh, M_ * 2048 / 4);
    convert_h4_1d<<<(3072 * 2048 / 4 + 255) / 256, blk>>>(
        (const float4*)wq_w, (uint2*)wqkva, 3072 * 2048 / 4);
    convert_h4_1d<<<(576 * 2048 / 4 + 255) / 256, blk>>>(
        (const float4*)wkva_w, (uint2*)(wqkva + (size_t)3072 * 2048), 576 * 2048 / 4);
    convert_h4_2d<<<dim3(1, 4096), blk>>>(wkvb_w, 513, wkvbh, KVN, 513);
    convert_h4_2d<<<dim3(3, 2047), blk>>>(wo_w, 2064, woh, KCT, 2064);
    biascat_kernel<<<15, blk>>>(wq_b, wkva_b, biasqa);

    // fused Q + KV-A projection: (4096x2048) @ (3712x2048)^T
    gemm_h1<<<dim3(29, 32), blk, DSMEM_H>>>(xh, 2048, wqkva, 2048,
                                            qkva, NQA, biasqa, 3648, 2048);
    rmsnorm_kpe_kernel<<<M_, blk>>>(qkva, kvnw, fc, fs, kvnh, kpe);
    // KV-B proj: (4096x576) @ (4096x576)^T  (576 = 9 chunks of 64)
    gemm_h1<<<dim3(32, 32), blk, DSMEM_H>>>(kvnh, KVN, wkvbh, KVN,
                                            kv2, 4096, wkvb_b, 4096, KVN);
    post_q_kernel<<<(M_ * H_) / 8, blk>>>(qkva, fc, fs, qsh, tq);
    post_kv_kernel<<<(M_ * H_) / 8, blk>>>(kv2, kpe, ksh, tk, vth, vtl);
    fused_attn<<<dim3(8, 64), blk, DSMEM_F>>>(qsh, ksh, tq, tk, vth, vtl, ch);
    // out proj: (4096x2112) @ (2047x2112)^T -> out[:,1:]  (2112 = 33 chunks)
    gemm_h1<<<dim3(16, 32), blk, DSMEM_H>>>(ch, KCT, woh, KCT,
                                            out + 1, 2048, wo_b, 2047, KCT);
    final_t_kernel<<<M_, blk>>>(out);
}

// round 16
// speedup vs baseline: 1.2042x; 1.0027x over previous
#include <cuda_runtime.h>
#include <cuda_fp16.h>
#include <math.h>
#include <stdint.h>

namespace {
constexpr int B_ = 4, S_ = 1024, H_ = 16;
constexpr int M_ = B_ * S_;
constexpr float SC2 = 0.14396396f * 1.44269504f;    // 2/sqrt(193) * log2(e)
constexpr int KQS = 192, KVN = 576, KCT = 2112, VDIM = 136;
constexpr int NQA = 3712;                            // 3072 (q) + 576 (kva) + 64 pad
constexpr size_t DSMEM_H = 2 * 2 * 18432;            // gemm: 2 stages x (A+B), BK=64, pitch 144
constexpr size_t DSMEM_F = 2 * 51200 + 2 * 34816 + 512;  // 172544
}

// fp32 scratch
__device__ float g_qkva[(size_t)M_ * NQA];
__device__ float g_kpe[(size_t)M_ * 64];
__device__ float g_kv2[(size_t)M_ * 4096];
__device__ float g_tq[(size_t)64 * S_], g_tk[(size_t)64 * S_];
__device__ float g_biasqa[NQA];
// fp16 projection operands
__device__ __half g_xh[(size_t)M_ * 2048];
__device__ __half g_wqkva[(size_t)NQA * 2048];       // rows 3648..3711 stay 0
__device__ __half g_kvnh[(size_t)M_ * KVN];
__device__ __half g_wkvbh[(size_t)4096 * KVN];
__device__ __half g_ch[(size_t)M_ * KCT];            // cols 2064..2111 stay 0
__device__ __half g_woh[(size_t)2048 * KCT];
// fp16 attention operands
__device__ __half g_qsh[(size_t)64 * S_ * KQS];
__device__ __half g_ksh[(size_t)64 * S_ * KQS];
__device__ __half g_vth[(size_t)64 * S_ * VDIM], g_vtl[(size_t)64 * S_ * VDIM];

__device__ __forceinline__ uint32_t cvta_smem(const void* p) {
    uint32_t a;
    asm("{ .reg .u64 t; cvta.to.shared.u64 t, %1; cvt.u32.u64 %0, t; }" : "=r"(a) : "l"(p));
    return a;
}
#define CPASYNC16(s, g) asm volatile("cp.async.cg.shared.global [%0], [%1], 16;" :: "r"(s), "l"(g) : "memory")
#define CPCOMMIT()      asm volatile("cp.async.commit_group;" ::: "memory")
#define CPWAIT(n)       asm volatile("cp.async.wait_group %0;" :: "n"(n) : "memory")

__device__ __forceinline__ float ex2f(float x) {
    float y;
    asm("ex2.approx.ftz.f32 %0, %1;" : "=f"(y) : "f"(x));
    return y;
}
__device__ __forceinline__ void ldsm_x4(uint32_t* r, uint32_t a) {
    asm volatile("ldmatrix.sync.aligned.m8n8.x4.shared.b16 {%0,%1,%2,%3}, [%4];"
                 : "=r"(r[0]), "=r"(r[1]), "=r"(r[2]), "=r"(r[3]) : "r"(a));
}
__device__ __forceinline__ void ldsm_x2(uint32_t* r, uint32_t a) {
    asm volatile("ldmatrix.sync.aligned.m8n8.x2.shared.b16 {%0,%1}, [%2];"
                 : "=r"(r[0]), "=r"(r[1]) : "r"(a));
}
__device__ __forceinline__ void ldsm_x2t(uint32_t* r, uint32_t a) {
    asm volatile("ldmatrix.sync.aligned.m8n8.x2.trans.shared.b16 {%0,%1}, [%2];"
                 : "=r"(r[0]), "=r"(r[1]) : "r"(a));
}
__device__ __forceinline__ void mma_f16(float* d, const uint32_t* a, const uint32_t* b) {
    asm volatile("mma.sync.aligned.m16n8k16.row.col.f32.f16.f16.f32 "
                 "{%0,%1,%2,%3}, {%4,%5,%6,%7}, {%8,%9}, {%0,%1,%2,%3};"
                 : "+f"(d[0]), "+f"(d[1]), "+f"(d[2]), "+f"(d[3])
                 : "r"(a[0]), "r"(a[1]), "r"(a[2]), "r"(a[3]), "r"(b[0]), "r"(b[1]));
}
__device__ __forceinline__ uint32_t packh2(float x, float y) {
    __half2 h = __floats2half2_rn(x, y);
    return *reinterpret_cast<uint32_t*>(&h);
}
__device__ __forceinline__ float warp_sum(float v) {
#pragma unroll
    for (int o = 16; o; o >>= 1) v += __shfl_xor_sync(0xffffffffu, v, o);
    return v;
}
__device__ __forceinline__ float block_sum_256(float v, float* sh) {
    int tid = threadIdx.x;
#pragma unroll
    for (int o = 16; o; o >>= 1) v += __shfl_xor_sync(0xffffffffu, v, o);
    __syncthreads();
    if ((tid & 31) == 0) sh[tid >> 5] = v;
    __syncthreads();
    if (tid < 32) {
        float t = (tid < 8) ? sh[tid] : 0.f;
#pragma unroll
        for (int o = 4; o; o >>= 1) t += __shfl_xor_sync(0xffffffffu, t, o);
        if (tid == 0) sh[0] = t;
    }
    __syncthreads();
    return sh[0];
}
__device__ __forceinline__ void hsplit(float v, __half* hi, __half* lo, long long i) {
    __half h = __float2half_rn(v);
    hi[i] = h;
    lo[i] = __float2half_rn(v - __half2float(h));
}
__device__ __forceinline__ uint2 pack4(float4 v) {
    __half2 a = __floats2half2_rn(v.x, v.y);
    __half2 b = __floats2half2_rn(v.z, v.w);
    uint2 o;
    o.x = *reinterpret_cast<uint32_t*>(&a);
    o.y = *reinterpret_cast<uint32_t*>(&b);
    return o;
}

// ====== fp16 GEMM: CTA 128x128, warp 64x32, BK=64 (pitch 144B), 2 CTAs/SM ======
__global__ void __launch_bounds__(256, 2)
gemm_h1(const __half* __restrict__ A, int lda,
        const __half* __restrict__ Bm, int ldb,
        float* __restrict__ C, int ldc,
        const float* __restrict__ bias, int Nreal, int K)
{
    const int bm = blockIdx.y * 128, bn = blockIdx.x * 128;
    const int nch = K >> 6;
    extern __shared__ __align__(16) char smem[];
    const uint32_t sbase = cvta_smem(smem);
    const int tid = threadIdx.x, wid = tid >> 5, lane = tid & 31;
    const int wm = (wid >> 2) * 64, wn = (wid & 3) * 32;

    float acc[4][4][4] = {};
    const __half* srcs[2] = {A, Bm};

    auto load_stage = [&](int s, int c) {
        const long long k0 = (long long)c * 64;
#pragma unroll
        for (int arr = 0; arr < 2; ++arr) {
            const __half* src = srcs[arr];
            const int ld = (arr == 0) ? lda : ldb;
            const int ro = (arr == 0) ? bm : bn;
            const uint32_t base = sbase + (uint32_t)s * 36864u + (uint32_t)arr * 18432u;
#pragma unroll
            for (int j = 0; j < 4; ++j) {
                const int cid = tid + j * 256;
                const int row = cid >> 3, ch = cid & 7;
                CPASYNC16(base + (uint32_t)(row * 144 + ch * 16),
                          src + (long long)(ro + row) * ld + k0 + ch * 8);
            }
        }
        CPCOMMIT();
    };

    load_stage(0, 0);
    for (int c = 0; c < nch; ++c) {
        if (c + 1 < nch) { load_stage((c + 1) & 1, c + 1); CPWAIT(1); }
        else             { CPWAIT(0); }
        __syncthreads();
        const uint32_t st = sbase + (uint32_t)(c & 1) * 36864u;
#pragma unroll
        for (int ks = 0; ks < 4; ++ks) {
            uint32_t ah[4][4], bh[4][2];
            const int arow = wm + (lane & 15);
            const int acol = ks * 16 + (lane >> 4) * 8;
#pragma unroll
            for (int mf = 0; mf < 4; ++mf)
                ldsm_x4(ah[mf], st + (uint32_t)((arow + mf * 16) * 144 + acol * 2));
            const int brow = wn + (lane & 7);
            const int bcol = ks * 16 + ((lane >> 3) & 1) * 8;
#pragma unroll
            for (int nf = 0; nf < 4; ++nf)
                ldsm_x2(bh[nf], st + 18432u + (uint32_t)((brow + nf * 8) * 144 + bcol * 2));
#pragma unroll
            for (int mf = 0; mf < 4; ++mf)
#pragma unroll
                for (int nf = 0; nf < 4; ++nf)
                    mma_f16(acc[mf][nf], ah[mf], bh[nf]);
        }
        __syncthreads();
    }
#pragma unroll
    for (int mf = 0; mf < 4; ++mf) {
        const long long r0 = bm + wm + mf * 16 + (lane >> 2);
#pragma unroll
        for (int nf = 0; nf < 4; ++nf) {
            const int col = bn + wn + nf * 8 + (lane & 3) * 2;
            const float b0 = bias ? bias[min(col, Nreal - 1)] : 0.f;
            const float b1 = bias ? bias[min(col + 1, Nreal - 1)] : 0.f;
            if (col < Nreal) {
                C[r0 * ldc + col] = acc[mf][nf][0] + b0;
                C[(r0 + 8) * ldc + col] = acc[mf][nf][2] + b0;
            }
            if (col + 1 < Nreal) {
                C[r0 * ldc + col + 1] = acc[mf][nf][1] + b1;
                C[(r0 + 8) * ldc + col + 1] = acc[mf][nf][3] + b1;
            }
        }
    }
}

// ============ fused flash-attention + Lorentz centroid ============
__global__ void __launch_bounds__(256, 1)
fused_attn(const __half* __restrict__ qsh, const __half* __restrict__ ksh,
           const float* __restrict__ tqg, const float* __restrict__ tkg,
           const __half* __restrict__ vh, const __half* __restrict__ vl,
           __half* __restrict__ ch)
{
    const int iq = 7 - (int)blockIdx.x;
    const int bh = (int)blockIdx.y;
    const long long qkbase = (long long)bh * S_ * KQS;
    const long long vgbase = (long long)bh * S_ * VDIM;
    extern __shared__ __align__(16) char smem[];
    const uint32_t sbase = cvta_smem(smem);
    const uint32_t vsH = sbase + 102400u, vsL = vsH + 34816u;
    float* tks = (float*)(smem + 102400u + 2 * 34816u);
    const int tid = threadIdx.x, w = tid >> 5, lane = tid & 31;

    const __half* qh_g = qsh + qkbase + (long long)iq * 128 * KQS;
    const float tq0 = tqg[(long long)bh * S_ + iq * 128 + w * 16 + (lane >> 2)];
    const float tq1 = tqg[(long long)bh * S_ + iq * 128 + w * 16 + (lane >> 2) + 8];

    auto load_tile192 = [&](uint32_t dst, const __half* src) {
#pragma unroll
        for (int t2 = 0; t2 < 12; ++t2) {
            const int idx = tid + t2 * 256;
            const int row = idx / 24, seg = idx % 24;
            CPASYNC16(dst + (uint32_t)(row * 400 + seg * 16),
                      src + (long long)row * KQS + seg * 8);
        }
        CPCOMMIT();
    };
    auto load_vtile = [&](int j) {
        for (int idx = tid; idx < 2176; idx += 256) {
            const int row = idx / 17, seg = idx % 17;
            const long long g = vgbase + (long long)(j * 128 + row) * VDIM + seg * 8;
            CPASYNC16(vsH + (uint32_t)(row * 272 + seg * 16), vh + g);
            CPASYNC16(vsL + (uint32_t)(row * 272 + seg * 16), vl + g);
        }
        CPCOMMIT();
    };

    uint32_t qf[12][4];
    {
        load_tile192(sbase, qh_g);
        CPWAIT(0);
        __syncthreads();
#pragma unroll
        for (int kk = 0; kk < 12; ++kk) {
            const uint32_t aoff =
                (uint32_t)((w * 16 + (lane & 15)) * 400 + (kk * 16 + (lane >> 4) * 8) * 2);
            ldsm_x4(qf[kk], sbase + aoff);
        }
        __syncthreads();
    }

    float O[17][4] = {};
    float m0 = -1e30f, m1 = -1e30f, l0 = 0.f, l1 = 0.f;

    load_tile192(sbase, ksh + qkbase);
    load_vtile(0);

    for (int j = 0; j <= iq; ++j) {
        const uint32_t kst = sbase + (uint32_t)(j & 1) * 51200u;
        const int jn = min(j + 1, iq);
        if (tid < 128) tks[tid] = tkg[(long long)bh * S_ + j * 128 + tid];
        load_tile192(sbase + (uint32_t)(jn & 1) * 51200u,
                     ksh + qkbase + (long long)jn * 128 * KQS);
        CPWAIT(2);
        __syncthreads();

        float acc[16][4] = {};
#pragma unroll
        for (int kc = 0; kc < 12; ++kc) {
#pragma unroll
            for (int nf = 0; nf < 16; ++nf) {
                const uint32_t boff =
                    (uint32_t)((nf * 8 + (lane & 7)) * 400 +
                               (kc * 16 + ((lane >> 3) & 1) * 8) * 2);
                uint32_t kk[2];
                ldsm_x2(kk, kst + boff);
                mma_f16(acc[nf], qf[kc], kk);
            }
        }
        {
            const int c0b = (lane & 3) * 2;
#pragma unroll
            for (int nf = 0; nf < 16; ++nf) {
                const float k0v = tks[nf * 8 + c0b], k1v = tks[nf * 8 + c0b + 1];
                acc[nf][0] -= tq0 * k0v; acc[nf][1] -= tq0 * k1v;
                acc[nf][2] -= tq1 * k0v; acc[nf][3] -= tq1 * k1v;
            }
        }
        if (j == iq) {
            const int rt0 = w * 16 + (lane >> 2), rt1 = rt0 + 8;
#pragma unroll
            for (int nf = 0; nf < 16; ++nf) {
                const int ct = nf * 8 + (lane & 3) * 2;
                if (ct > rt0)     acc[nf][0] = -1e30f;
                if (ct + 1 > rt0) acc[nf][1] = -1e30f;
                if (ct > rt1)     acc[nf][2] = -1e30f;
                if (ct + 1 > rt1) acc[nf][3] = -1e30f;
            }
        }
        float mx0 = -1e30f, mx1 = -1e30f;
#pragma unroll
        for (int nf = 0; nf < 16; ++nf) {
            mx0 = fmaxf(mx0, fmaxf(acc[nf][0], acc[nf][1]));
            mx1 = fmaxf(mx1, fmaxf(acc[nf][2], acc[nf][3]));
        }
        mx0 = fmaxf(mx0, __shfl_xor_sync(~0u, mx0, 1));
        mx0 = fmaxf(mx0, __shfl_xor_sync(~0u, mx0, 2));
        mx1 = fmaxf(mx1, __shfl_xor_sync(~0u, mx1, 1));
        mx1 = fmaxf(mx1, __shfl_xor_sync(~0u, mx1, 2));
        const float mn0 = fmaxf(m0, mx0), mn1 = fmaxf(m1, mx1);
        const float a0 = ex2f((m0 - mn0) * SC2), a1 = ex2f((m1 - mn1) * SC2);
        l0 *= a0; l1 *= a1;
#pragma unroll
        for (int nf = 0; nf < 17; ++nf) {
            O[nf][0] *= a0; O[nf][1] *= a0; O[nf][2] *= a1; O[nf][3] *= a1;
        }
        float s0 = 0.f, s1 = 0.f;
#pragma unroll
        for (int nf = 0; nf < 16; ++nf) {
            acc[nf][0] = ex2f((acc[nf][0] - mn0) * SC2);
            acc[nf][1] = ex2f((acc[nf][1] - mn0) * SC2);
            acc[nf][2] = ex2f((acc[nf][2] - mn1) * SC2);
            acc[nf][3] = ex2f((acc[nf][3] - mn1) * SC2);
            s0 += acc[nf][0] + acc[nf][1];
            s1 += acc[nf][2] + acc[nf][3];
        }
        s0 += __shfl_xor_sync(~0u, s0, 1); s0 += __shfl_xor_sync(~0u, s0, 2);
        s1 += __shfl_xor_sync(~0u, s1, 1); s1 += __shfl_xor_sync(~0u, s1, 2);
        l0 += s0; l1 += s1; m0 = mn0; m1 = mn1;

        CPWAIT(1);
        __syncthreads();
#pragma unroll
        for (int kf = 0; kf < 8; ++kf) {
            uint32_t Ph[4];
            Ph[0] = packh2(acc[2 * kf][0], acc[2 * kf][1]);
            Ph[1] = packh2(acc[2 * kf][2], acc[2 * kf][3]);
            Ph[2] = packh2(acc[2 * kf + 1][0], acc[2 * kf + 1][1]);
            Ph[3] = packh2(acc[2 * kf + 1][2], acc[2 * kf + 1][3]);
            const uint32_t vrow = (uint32_t)((kf * 16 + (lane & 15)) * 272);
#pragma unroll
            for (int nf = 0; nf < 17; ++nf) {
                uint32_t vh2[2], vl2[2];
                ldsm_x2t(vh2, vsH + vrow + (uint32_t)(nf * 16));
                ldsm_x2t(vl2, vsL + vrow + (uint32_t)(nf * 16));
                mma_f16(O[nf], Ph, vh2);
                mma_f16(O[nf], Ph, vl2);
            }
        }
        __syncthreads();
        load_vtile(jn);
    }
    const float i0 = 1.f / l0, i1 = 1.f / l1;
    float ss0 = 0.f, ss1 = 0.f;
#pragma unroll
    for (int nf = 0; nf < 17; ++nf) {
        O[nf][0] *= i0; O[nf][1] *= i0; O[nf][2] *= i1; O[nf][3] *= i1;
        ss0 += O[nf][0] * O[nf][0] + O[nf][1] * O[nf][1];
        ss1 += O[nf][2] * O[nf][2] + O[nf][3] * O[nf][3];
    }
    ss0 += __shfl_xor_sync(~0u, ss0, 1); ss0 += __shfl_xor_sync(~0u, ss0, 2);
    ss1 += __shfl_xor_sync(~0u, ss1, 1); ss1 += __shfl_xor_sync(~0u, ss1, 2);
    const float t0 = __shfl_sync(~0u, O[0][0], lane & ~3);
    const float t1 = __shfl_sync(~0u, O[0][2], lane & ~3);
    const float d0 = rsqrtf(fmaxf(fabsf(2.f * t0 * t0 - ss0), 1e-8f));
    const float d1 = rsqrtf(fmaxf(fabsf(2.f * t1 * t1 - ss1), 1e-8f));
    const int hh = bh & 15;
    const long long tok0 = (long long)(bh >> 4) * 1024 + iq * 128 + w * 16 + (lane >> 2);
    const long long o0 = tok0 * KCT + hh * 129, o1 = (tok0 + 8) * KCT + hh * 129;
#pragma unroll
    for (int nf = 0; nf < 17; ++nf) {
        const int cc = nf * 8 + (lane & 3) * 2;
        if (cc < 129) {
            ch[o0 + cc] = __float2half_rn(O[nf][0] * d0);
            ch[o1 + cc] = __float2half_rn(O[nf][2] * d1);
        }
        if (cc + 1 < 129) {
            ch[o0 + cc + 1] = __float2half_rn(O[nf][1] * d0);
            ch[o1 + cc + 1] = __float2half_rn(O[nf][3] * d1);
        }
    }
}

// ---------- elementwise (vectorized, 4x ILP) ----------
__global__ void __launch_bounds__(256)
convert_h4_1d(const float4* __restrict__ src, uint2* __restrict__ dst, int n4)
{
    const int base = blockIdx.x * 1024 + threadIdx.x;
#pragma unroll
    for (int j = 0; j < 4; ++j) {
        const int idx = base + j * 256;
        if (idx < n4) dst[idx] = pack4(src[idx]);
    }
}

__global__ void __launch_bounds__(256)
convert_h4_2d(const float* __restrict__ src, int lds,
              __half* __restrict__ dst, int ldd, int cols)
{
    const int r = blockIdx.y;
    const int c4 = blockIdx.x * 256 + threadIdx.x;
    const int cols4 = cols >> 2;
    if (c4 < cols4) {
        const float* p = src + (long long)r * lds + c4 * 4;
        float4 v;
        v.x = p[0]; v.y = p[1]; v.z = p[2]; v.w = p[3];
        *(uint2*)(dst + (long long)r * ldd + c4 * 4) = pack4(v);
    } else if (c4 < cols4 + (cols & 3)) {
        const int c = cols4 * 4 + (c4 - cols4);
        dst[(long long)r * ldd + c] = __float2half_rn(src[(long long)r * lds + c]);
    }
}

__global__ void __launch_bounds__(256)
biascat_kernel(const float* __restrict__ a, const float* __restrict__ b,
               float* __restrict__ dst)
{
    const int i = blockIdx.x * 256 + threadIdx.x;
    if (i >= NQA) return;
    if (i < 3072) dst[i] = a[i];
    else if (i < 3648) dst[i] = b[i - 3072];
    else dst[i] = 0.f;
}

__global__ void __launch_bounds__(256)
rmsnorm_kpe_kernel(const float* __restrict__ qkva, const float* __restrict__ w,
                   const float* __restrict__ fc, const float* __restrict__ fs,
                   __half* __restrict__ kvnh, float* __restrict__ kpe)
{
    const int tok = blockIdx.x, s = tok & (S_ - 1), tid = threadIdx.x;
    const float* in = qkva + (size_t)tok * NQA + 3072;
    __shared__ float sp[512];
    __shared__ float sh[8];
    float local = 0.f;
    for (int i = tid; i < 512; i += 256) { float v = in[i]; local += v * v; }
    float r = rsqrtf(block_sum_256(local, sh) * (1.0f / 512.f) + 1e-6f);
    float l2 = 0.f;
    for (int i = tid; i < 512; i += 256) {
        float v = in[i] * r * w[i];
        sp[i] = v;
        l2 += v * v;
    }
    float tot2 = block_sum_256(l2, sh);
    const long long ob = (long long)tok * KVN;
    if (tid == 0) kvnh[ob] = __float2half_rn(sqrtf(tot2 + 1.f));
    for (int i = tid; i < 512; i += 256) kvnh[ob + 1 + i] = __float2half_rn(sp[i]);
    if (tid < 32) {
        float x1 = in[512 + 2 * tid], x2 = in[512 + 2 * tid + 1];
        float c = fc[s * 32 + tid], sn = fs[s * 32 + tid];
        kpe[(size_t)tok * 64 + 2 * tid]     = x1 * c - x2 * sn;
        kpe[(size_t)tok * 64 + 2 * tid + 1] = x1 * sn + x2 * c;
    }
}

__global__ void __launch_bounds__(256)
post_q_kernel(const float* __restrict__ qkva, const float* __restrict__ fc,
              const float* __restrict__ fs,
              __half* __restrict__ qshp, float* __restrict__ tq)
{
    const int gw = (blockIdx.x * blockDim.x + threadIdx.x) >> 5, lane = threadIdx.x & 31;
    if (gw >= M_ * H_) return;
    const int h = gw % H_, tok = gw / H_, b = tok / S_, s = tok & (S_ - 1);
    const float* qr = qkva + (size_t)tok * NQA + h * 192;
    const float4 qv = *(const float4*)(qr + lane * 4);
    const float c = fc[s * 32 + lane], sn = fs[s * 32 + lane];
    const float x1 = qr[128 + 2 * lane], x2 = qr[128 + 2 * lane + 1];
    const float r0 = x1 * c - x2 * sn, r1 = x1 * sn + x2 * c;
    float ss = r0 * r0 + r1 * r1 + qv.x * qv.x + qv.y * qv.y + qv.z * qv.z + qv.w * qv.w;
    ss = warp_sum(ss);
    const long long row = ((long long)b * H_ + h) * S_ + s;
    if (lane == 0) tq[row] = sqrtf(ss + 1.f);
    const long long ob = row * KQS;
    *(uint2*)(qshp + ob + lane * 4) = pack4(qv);
    *(__half2*)(qshp + ob + 128 + 2 * lane) = __floats2half2_rn(r0, r1);
}

__global__ void __launch_bounds__(256)
post_kv_kernel(const float* __restrict__ kv2, const float* __restrict__ kpe,
               __half* __restrict__ kshp, float* __restrict__ tk,
               __half* __restrict__ vhp, __half* __restrict__ vlp)
{
    const int gw = (blockIdx.x * blockDim.x + threadIdx.x) >> 5, lane = threadIdx.x & 31;
    if (gw >= M_ * H_) return;
    const int h = gw % H_, tok = gw / H_, b = tok / S_, s = tok & (S_ - 1);
    const float* row = kv2 + ((size_t)tok * H_ + h) * 256;
    const float* pe = kpe + (size_t)tok * 64;
    const float4 kn = *(const float4*)(row + lane * 4);
    const float2 pp = *(const float2*)(pe + lane * 2);
    float ss = kn.x * kn.x + kn.y * kn.y + kn.z * kn.z + kn.w * kn.w + pp.x * pp.x + pp.y * pp.y;
    ss = warp_sum(ss);
    const long long krow = ((long long)b * H_ + h) * S_ + s;
    if (lane == 0) tk[krow] = sqrtf(ss + 1.f);
    const long long kb = krow * KQS;
    *(uint2*)(kshp + kb + lane * 4) = pack4(kn);
    *(__half2*)(kshp + kb + 128 + 2 * lane) = __floats2half2_rn(pp.x, pp.y);
    const float4 vv = *(const float4*)(row + 128 + lane * 4);
    float sv = vv.x * vv.x + vv.y * vv.y + vv.z * vv.z + vv.w * vv.w;
    sv = warp_sum(sv);
    const long long vb = ((long long)b * H_ + h) * S_ * VDIM + (long long)s * VDIM;
    if (lane == 0) hsplit(sqrtf(sv + 1.f), vhp, vlp, vb);
    hsplit(vv.x, vhp, vlp, vb + 1 + lane * 4);
    hsplit(vv.y, vhp, vlp, vb + 2 + lane * 4);
    hsplit(vv.z, vhp, vlp, vb + 3 + lane * 4);
    hsplit(vv.w, vhp, vlp, vb + 4 + lane * 4);
}

__global__ void __launch_bounds__(256)
final_t_kernel(float* __restrict__ out)
{
    const int row = blockIdx.x, tid = threadIdx.x;
    float* p = out + (size_t)row * 2048;
    __shared__ float sh[8];
    float local = 0.f;
    for (int i = 1 + tid; i < 2048; i += 256) { float v = p[i]; local += v * v; }
    float tot = block_sum_256(local, sh);
    if (tid == 0) p[0] = sqrtf(tot + 1.f);
}

extern "C" void kernel_launch(void* const* d_in, const int* in_sizes, int n_in,
                              void* d_out, int out_size)
{
    (void)in_sizes; (void)n_in; (void)out_size;
    const float* x      = (const float*)d_in[0];
    const float* fc     = (const float*)d_in[1];
    const float* fs     = (const float*)d_in[2];
    const float* wq_w   = (const float*)d_in[4];
    const float* wq_b   = (const float*)d_in[5];
    const float* wkva_w = (const float*)d_in[6];
    const float* wkva_b = (const float*)d_in[7];
    const float* kvnw   = (const float*)d_in[8];
    const float* wkvb_w = (const float*)d_in[9];
    const float* wkvb_b = (const float*)d_in[10];
    const float* wo_w   = (const float*)d_in[11];
    const float* wo_b   = (const float*)d_in[12];
    float* out = (float*)d_out;

    float *qkva, *kpe, *kv2, *tq, *tk, *biasqa;
    cudaGetSymbolAddress((void**)&qkva, g_qkva);
    cudaGetSymbolAddress((void**)&kpe, g_kpe);
    cudaGetSymbolAddress((void**)&kv2, g_kv2);
    cudaGetSymbolAddress((void**)&tq, g_tq);
    cudaGetSymbolAddress((void**)&tk, g_tk);
    cudaGetSymbolAddress((void**)&biasqa, g_biasqa);
    __half *xh, *wqkva, *kvnh, *wkvbh, *ch, *woh, *qsh, *ksh, *vth, *vtl;
    cudaGetSymbolAddress((void**)&xh, g_xh);
    cudaGetSymbolAddress((void**)&wqkva, g_wqkva);
    cudaGetSymbolAddress((void**)&kvnh, g_kvnh);
    cudaGetSymbolAddress((void**)&wkvbh, g_wkvbh);
    cudaGetSymbolAddress((void**)&ch, g_ch);
    cudaGetSymbolAddress((void**)&woh, g_woh);
    cudaGetSymbolAddress((void**)&qsh, g_qsh);
    cudaGetSymbolAddress((void**)&ksh, g_ksh);
    cudaGetSymbolAddress((void**)&vth, g_vth);
    cudaGetSymbolAddress((void**)&vtl, g_vtl);

    cudaFuncSetAttribute(gemm_h1, cudaFuncAttributeMaxDynamicSharedMemorySize, (int)DSMEM_H);
    cudaFuncSetAttribute(fused_attn, cudaFuncAttributeMaxDynamicSharedMemorySize, (int)DSMEM_F);

    const dim3 blk(256);
    convert_h4_1d<<<(M_ * 2048 / 4 + 1023) / 1024, blk>>>(
        (const float4*)x, (uint2*)xh, M_ * 2048 / 4);
    convert_h4_1d<<<(3072 * 2048 / 4 + 1023) / 1024, blk>>>(
        (const float4*)wq_w, (uint2*)wqkva, 3072 * 2048 / 4);
    convert_h4_1d<<<(576 * 2048 / 4 + 1023) / 1024, blk>>>(
        (const float4*)wkva_w, (uint2*)(wqkva + (size_t)3072 * 2048), 576 * 2048 / 4);
    convert_h4_2d<<<dim3(1, 4096), blk>>>(wkvb_w, 513, wkvbh, KVN, 513);
    convert_h4_2d<<<dim3(3, 2047), blk>>>(wo_w, 2064, woh, KCT, 2064);
    biascat_kernel<<<15, blk>>>(wq_b, wkva_b, biasqa);

    // fused Q + KV-A projection: (4096x2048) @ (3712x2048)^T
    gemm_h1<<<dim3(29, 32), blk, DSMEM_H>>>(xh, 2048, wqkva, 2048,
                                            qkva, NQA, biasqa, 3648, 2048);
    rmsnorm_kpe_kernel<<<M_, blk>>>(qkva, kvnw, fc, fs, kvnh, kpe);
    // KV-B proj: (4096x576) @ (4096x576)^T
    gemm_h1<<<dim3(32, 32), blk, DSMEM_H>>>(kvnh, KVN, wkvbh, KVN,
                                            kv2, 4096, wkvb_b, 4096, KVN);
    post_q_kernel<<<(M_ * H_) / 8, blk>>>(qkva, fc, fs, qsh, tq);
    post_kv_kernel<<<(M_ * H_) / 8, blk>>>(kv2, kpe, ksh, tk, vth, vtl);
    fused_attn<<<dim3(8, 64), blk, DSMEM_F>>>(qsh, ksh, tq, tk, vth, vtl, ch);
    // out proj: (4096x2112) @ (2047x2112)^T -> out[:,1:]
    gemm_h1<<<dim3(16, 32), blk, DSMEM_H>>>(ch, KCT, woh, KCT,
                                            out + 1, 2048, wo_b, 2047, KCT);
    final_t_kernel<<<M_, blk>>>(out);
}

// round 17
// speedup vs baseline: 1.2561x; 1.0431x over previous
#include <cuda_runtime.h>
#include <cuda_fp16.h>
#include <math.h>
#include <stdint.h>
#include <type_traits>

namespace {
constexpr int B_ = 4, S_ = 1024, H_ = 16;
constexpr int M_ = B_ * S_;
constexpr float SC2 = 0.14396396f * 1.44269504f;    // 2/sqrt(193) * log2(e)
constexpr int KQS = 192, KVN = 576, KCT = 2112, VDIM = 136;
constexpr int NQA = 3712;                            // 3072 (q) + 576 (kva) + 64 pad
constexpr size_t DSMEM_H = 2 * 2 * 18432;            // gemm: 2 stages x (A+B), BK=64, pitch 144
constexpr size_t DSMEM_F = 2 * 51200 + 2 * 34816 + 512;  // 172544
// unified convert job bounds (16B-chunk units)
constexpr int E0 = 2097152;                 // x
constexpr int E1 = E0 + 1572864;            // wq
constexpr int E2 = E1 + 294912;             // wkva
constexpr int E3 = E2 + 4096 * 129;         // wkvb (128 vec + 1 scalar per row)
constexpr int E4 = E3 + 2047 * 516;         // wo
constexpr int E5 = E4 + 928;                // biascat
}

// fp32 scratch
__device__ float g_kpe[(size_t)M_ * 64];
__device__ float g_kv2[(size_t)M_ * 4096];
__device__ float g_tq[(size_t)64 * S_], g_tk[(size_t)64 * S_];
__device__ float g_biasqa[NQA];
// fp16
__device__ __half g_qkvah[(size_t)M_ * NQA];
__device__ __half g_xh[(size_t)M_ * 2048];
__device__ __half g_wqkva[(size_t)NQA * 2048];       // rows 3648..3711 stay 0
__device__ __half g_kvnh[(size_t)M_ * KVN];
__device__ __half g_wkvbh[(size_t)4096 * KVN];
__device__ __half g_ch[(size_t)M_ * KCT];            // cols 2064..2111 stay 0
__device__ __half g_woh[(size_t)2048 * KCT];
__device__ __half g_qsh[(size_t)64 * S_ * KQS];
__device__ __half g_ksh[(size_t)64 * S_ * KQS];
__device__ __half g_vth[(size_t)64 * S_ * VDIM], g_vtl[(size_t)64 * S_ * VDIM];

__device__ __forceinline__ uint32_t cvta_smem(const void* p) {
    uint32_t a;
    asm("{ .reg .u64 t; cvta.to.shared.u64 t, %1; cvt.u32.u64 %0, t; }" : "=r"(a) : "l"(p));
    return a;
}
#define CPASYNC16(s, g) asm volatile("cp.async.cg.shared.global [%0], [%1], 16;" :: "r"(s), "l"(g) : "memory")
#define CPCOMMIT()      asm volatile("cp.async.commit_group;" ::: "memory")
#define CPWAIT(n)       asm volatile("cp.async.wait_group %0;" :: "n"(n) : "memory")

__device__ __forceinline__ float ex2f(float x) {
    float y;
    asm("ex2.approx.ftz.f32 %0, %1;" : "=f"(y) : "f"(x));
    return y;
}
__device__ __forceinline__ void ldsm_x4(uint32_t* r, uint32_t a) {
    asm volatile("ldmatrix.sync.aligned.m8n8.x4.shared.b16 {%0,%1,%2,%3}, [%4];"
                 : "=r"(r[0]), "=r"(r[1]), "=r"(r[2]), "=r"(r[3]) : "r"(a));
}
__device__ __forceinline__ void ldsm_x2(uint32_t* r, uint32_t a) {
    asm volatile("ldmatrix.sync.aligned.m8n8.x2.shared.b16 {%0,%1}, [%2];"
                 : "=r"(r[0]), "=r"(r[1]) : "r"(a));
}
__device__ __forceinline__ void ldsm_x2t(uint32_t* r, uint32_t a) {
    asm volatile("ldmatrix.sync.aligned.m8n8.x2.trans.shared.b16 {%0,%1}, [%2];"
                 : "=r"(r[0]), "=r"(r[1]) : "r"(a));
}
__device__ __forceinline__ void mma_f16(float* d, const uint32_t* a, const uint32_t* b) {
    asm volatile("mma.sync.aligned.m16n8k16.row.col.f32.f16.f16.f32 "
                 "{%0,%1,%2,%3}, {%4,%5,%6,%7}, {%8,%9}, {%0,%1,%2,%3};"
                 : "+f"(d[0]), "+f"(d[1]), "+f"(d[2]), "+f"(d[3])
                 : "r"(a[0]), "r"(a[1]), "r"(a[2]), "r"(a[3]), "r"(b[0]), "r"(b[1]));
}
__device__ __forceinline__ uint32_t packh2(float x, float y) {
    __half2 h = __floats2half2_rn(x, y);
    return *reinterpret_cast<uint32_t*>(&h);
}
__device__ __forceinline__ float warp_sum(float v) {
#pragma unroll
    for (int o = 16; o; o >>= 1) v += __shfl_xor_sync(0xffffffffu, v, o);
    return v;
}
__device__ __forceinline__ float block_sum_256(float v, float* sh) {
    int tid = threadIdx.x;
#pragma unroll
    for (int o = 16; o; o >>= 1) v += __shfl_xor_sync(0xffffffffu, v, o);
    __syncthreads();
    if ((tid & 31) == 0) sh[tid >> 5] = v;
    __syncthreads();
    if (tid < 32) {
        float t = (tid < 8) ? sh[tid] : 0.f;
#pragma unroll
        for (int o = 4; o; o >>= 1) t += __shfl_xor_sync(0xffffffffu, t, o);
        if (tid == 0) sh[0] = t;
    }
    __syncthreads();
    return sh[0];
}
__device__ __forceinline__ void hsplit(float v, __half* hi, __half* lo, long long i) {
    __half h = __float2half_rn(v);
    hi[i] = h;
    lo[i] = __float2half_rn(v - __half2float(h));
}
__device__ __forceinline__ uint2 pack4(float4 v) {
    __half2 a = __floats2half2_rn(v.x, v.y);
    __half2 b = __floats2half2_rn(v.z, v.w);
    uint2 o;
    o.x = *reinterpret_cast<uint32_t*>(&a);
    o.y = *reinterpret_cast<uint32_t*>(&b);
    return o;
}

// ====== fp16 GEMM: CTA 128x128, warp 64x32, BK=64, 2 CTAs/SM; OUT = float|half ======
template <typename TOUT>
__global__ void __launch_bounds__(256, 2)
gemm_h1(const __half* __restrict__ A, int lda,
        const __half* __restrict__ Bm, int ldb,
        TOUT* __restrict__ C, int ldc,
        const float* __restrict__ bias, int Nreal, int K)
{
    const int bm = blockIdx.y * 128, bn = blockIdx.x * 128;
    const int nch = K >> 6;
    extern __shared__ __align__(16) char smem[];
    const uint32_t sbase = cvta_smem(smem);
    const int tid = threadIdx.x, wid = tid >> 5, lane = tid & 31;
    const int wm = (wid >> 2) * 64, wn = (wid & 3) * 32;

    float acc[4][4][4] = {};
    const __half* srcs[2] = {A, Bm};

    auto load_stage = [&](int s, int c) {
        const long long k0 = (long long)c * 64;
#pragma unroll
        for (int arr = 0; arr < 2; ++arr) {
            const __half* src = srcs[arr];
            const int ld = (arr == 0) ? lda : ldb;
            const int ro = (arr == 0) ? bm : bn;
            const uint32_t base = sbase + (uint32_t)s * 36864u + (uint32_t)arr * 18432u;
#pragma unroll
            for (int j = 0; j < 4; ++j) {
                const int cid = tid + j * 256;
                const int row = cid >> 3, ch = cid & 7;
                CPASYNC16(base + (uint32_t)(row * 144 + ch * 16),
                          src + (long long)(ro + row) * ld + k0 + ch * 8);
            }
        }
        CPCOMMIT();
    };

    load_stage(0, 0);
    for (int c = 0; c < nch; ++c) {
        if (c + 1 < nch) { load_stage((c + 1) & 1, c + 1); CPWAIT(1); }
        else             { CPWAIT(0); }
        __syncthreads();
        const uint32_t st = sbase + (uint32_t)(c & 1) * 36864u;
#pragma unroll
        for (int ks = 0; ks < 4; ++ks) {
            uint32_t ah[4][4], bh[4][2];
            const int arow = wm + (lane & 15);
            const int acol = ks * 16 + (lane >> 4) * 8;
#pragma unroll
            for (int mf = 0; mf < 4; ++mf)
                ldsm_x4(ah[mf], st + (uint32_t)((arow + mf * 16) * 144 + acol * 2));
            const int brow = wn + (lane & 7);
            const int bcol = ks * 16 + ((lane >> 3) & 1) * 8;
#pragma unroll
            for (int nf = 0; nf < 4; ++nf)
                ldsm_x2(bh[nf], st + 18432u + (uint32_t)((brow + nf * 8) * 144 + bcol * 2));
#pragma unroll
            for (int mf = 0; mf < 4; ++mf)
#pragma unroll
                for (int nf = 0; nf < 4; ++nf)
                    mma_f16(acc[mf][nf], ah[mf], bh[nf]);
        }
        __syncthreads();
    }
#pragma unroll
    for (int mf = 0; mf < 4; ++mf) {
        const long long r0 = bm + wm + mf * 16 + (lane >> 2);
#pragma unroll
        for (int nf = 0; nf < 4; ++nf) {
            const int col = bn + wn + nf * 8 + (lane & 3) * 2;
            const float b0 = bias ? bias[min(col, Nreal - 1)] : 0.f;
            const float b1 = bias ? bias[min(col + 1, Nreal - 1)] : 0.f;
            const float v0 = acc[mf][nf][0] + b0, v1 = acc[mf][nf][1] + b1;
            const float v2 = acc[mf][nf][2] + b0, v3 = acc[mf][nf][3] + b1;
            if constexpr (std::is_same<TOUT, __half>::value) {
                if (col + 1 < Nreal) {
                    *(__half2*)(C + r0 * ldc + col) = __floats2half2_rn(v0, v1);
                    *(__half2*)(C + (r0 + 8) * ldc + col) = __floats2half2_rn(v2, v3);
                } else if (col < Nreal) {
                    C[r0 * ldc + col] = __float2half_rn(v0);
                    C[(r0 + 8) * ldc + col] = __float2half_rn(v2);
                }
            } else {
                if (col < Nreal) {
                    C[r0 * ldc + col] = v0;
                    C[(r0 + 8) * ldc + col] = v2;
                }
                if (col + 1 < Nreal) {
                    C[r0 * ldc + col + 1] = v1;
                    C[(r0 + 8) * ldc + col + 1] = v3;
                }
            }
        }
    }
}

// ============ fused flash-attention + Lorentz centroid (R15-proven) ============
__global__ void __launch_bounds__(256, 1)
fused_attn(const __half* __restrict__ qsh, const __half* __restrict__ ksh,
           const float* __restrict__ tqg, const float* __restrict__ tkg,
           const __half* __restrict__ vh, const __half* __restrict__ vl,
           __half* __restrict__ ch)
{
    const int iq = 7 - (int)blockIdx.x;
    const int bh = (int)blockIdx.y;
    const long long qkbase = (long long)bh * S_ * KQS;
    const long long vgbase = (long long)bh * S_ * VDIM;
    extern __shared__ __align__(16) char smem[];
    const uint32_t sbase = cvta_smem(smem);
    const uint32_t vsH = sbase + 102400u, vsL = vsH + 34816u;
    float* tks = (float*)(smem + 102400u + 2 * 34816u);
    const int tid = threadIdx.x, w = tid >> 5, lane = tid & 31;

    const __half* qh_g = qsh + qkbase + (long long)iq * 128 * KQS;
    const float tq0 = tqg[(long long)bh * S_ + iq * 128 + w * 16 + (lane >> 2)];
    const float tq1 = tqg[(long long)bh * S_ + iq * 128 + w * 16 + (lane >> 2) + 8];

    auto load_tile192 = [&](uint32_t dst, const __half* src) {
#pragma unroll
        for (int t2 = 0; t2 < 12; ++t2) {
            const int idx = tid + t2 * 256;
            const int row = idx / 24, seg = idx % 24;
            CPASYNC16(dst + (uint32_t)(row * 400 + seg * 16),
                      src + (long long)row * KQS + seg * 8);
        }
        CPCOMMIT();
    };
    auto load_vtile = [&](int j) {
        for (int idx = tid; idx < 2176; idx += 256) {
            const int row = idx / 17, seg = idx % 17;
            const long long g = vgbase + (long long)(j * 128 + row) * VDIM + seg * 8;
            CPASYNC16(vsH + (uint32_t)(row * 272 + seg * 16), vh + g);
            CPASYNC16(vsL + (uint32_t)(row * 272 + seg * 16), vl + g);
        }
        CPCOMMIT();
    };

    uint32_t qf[12][4];
    {
        load_tile192(sbase, qh_g);
        CPWAIT(0);
        __syncthreads();
#pragma unroll
        for (int kk = 0; kk < 12; ++kk) {
            const uint32_t aoff =
                (uint32_t)((w * 16 + (lane & 15)) * 400 + (kk * 16 + (lane >> 4) * 8) * 2);
            ldsm_x4(qf[kk], sbase + aoff);
        }
        __syncthreads();
    }

    float O[17][4] = {};
    float m0 = -1e30f, m1 = -1e30f, l0 = 0.f, l1 = 0.f;

    load_tile192(sbase, ksh + qkbase);
    load_vtile(0);

    for (int j = 0; j <= iq; ++j) {
        const uint32_t kst = sbase + (uint32_t)(j & 1) * 51200u;
        const int jn = min(j + 1, iq);
        if (tid < 128) tks[tid] = tkg[(long long)bh * S_ + j * 128 + tid];
        load_tile192(sbase + (uint32_t)(jn & 1) * 51200u,
                     ksh + qkbase + (long long)jn * 128 * KQS);
        CPWAIT(2);
        __syncthreads();

        float acc[16][4] = {};
#pragma unroll
        for (int kc = 0; kc < 12; ++kc) {
#pragma unroll
            for (int nf = 0; nf < 16; ++nf) {
                const uint32_t boff =
                    (uint32_t)((nf * 8 + (lane & 7)) * 400 +
                               (kc * 16 + ((lane >> 3) & 1) * 8) * 2);
                uint32_t kk[2];
                ldsm_x2(kk, kst + boff);
                mma_f16(acc[nf], qf[kc], kk);
            }
        }
        {
            const int c0b = (lane & 3) * 2;
#pragma unroll
            for (int nf = 0; nf < 16; ++nf) {
                const float k0v = tks[nf * 8 + c0b], k1v = tks[nf * 8 + c0b + 1];
                acc[nf][0] -= tq0 * k0v; acc[nf][1] -= tq0 * k1v;
                acc[nf][2] -= tq1 * k0v; acc[nf][3] -= tq1 * k1v;
            }
        }
        if (j == iq) {
            const int rt0 = w * 16 + (lane >> 2), rt1 = rt0 + 8;
#pragma unroll
            for (int nf = 0; nf < 16; ++nf) {
                const int ct = nf * 8 + (lane & 3) * 2;
                if (ct > rt0)     acc[nf][0] = -1e30f;
                if (ct + 1 > rt0) acc[nf][1] = -1e30f;
                if (ct > rt1)     acc[nf][2] = -1e30f;
                if (ct + 1 > rt1) acc[nf][3] = -1e30f;
            }
        }
        float mx0 = -1e30f, mx1 = -1e30f;
#pragma unroll
        for (int nf = 0; nf < 16; ++nf) {
            mx0 = fmaxf(mx0, fmaxf(acc[nf][0], acc[nf][1]));
            mx1 = fmaxf(mx1, fmaxf(acc[nf][2], acc[nf][3]));
        }
        mx0 = fmaxf(mx0, __shfl_xor_sync(~0u, mx0, 1));
        mx0 = fmaxf(mx0, __shfl_xor_sync(~0u, mx0, 2));
        mx1 = fmaxf(mx1, __shfl_xor_sync(~0u, mx1, 1));
        mx1 = fmaxf(mx1, __shfl_xor_sync(~0u, mx1, 2));
        const float mn0 = fmaxf(m0, mx0), mn1 = fmaxf(m1, mx1);
        const float a0 = ex2f((m0 - mn0) * SC2), a1 = ex2f((m1 - mn1) * SC2);
        l0 *= a0; l1 *= a1;
#pragma unroll
        for (int nf = 0; nf < 17; ++nf) {
            O[nf][0] *= a0; O[nf][1] *= a0; O[nf][2] *= a1; O[nf][3] *= a1;
        }
        float s0 = 0.f, s1 = 0.f;
#pragma unroll
        for (int nf = 0; nf < 16; ++nf) {
            acc[nf][0] = ex2f((acc[nf][0] - mn0) * SC2);
            acc[nf][1] = ex2f((acc[nf][1] - mn0) * SC2);
            acc[nf][2] = ex2f((acc[nf][2] - mn1) * SC2);
            acc[nf][3] = ex2f((acc[nf][3] - mn1) * SC2);
            s0 += acc[nf][0] + acc[nf][1];
            s1 += acc[nf][2] + acc[nf][3];
        }
        s0 += __shfl_xor_sync(~0u, s0, 1); s0 += __shfl_xor_sync(~0u, s0, 2);
        s1 += __shfl_xor_sync(~0u, s1, 1); s1 += __shfl_xor_sync(~0u, s1, 2);
        l0 += s0; l1 += s1; m0 = mn0; m1 = mn1;

        CPWAIT(1);
        __syncthreads();
#pragma unroll
        for (int kf = 0; kf < 8; ++kf) {
            uint32_t Ph[4];
            Ph[0] = packh2(acc[2 * kf][0], acc[2 * kf][1]);
            Ph[1] = packh2(acc[2 * kf][2], acc[2 * kf][3]);
            Ph[2] = packh2(acc[2 * kf + 1][0], acc[2 * kf + 1][1]);
            Ph[3] = packh2(acc[2 * kf + 1][2], acc[2 * kf + 1][3]);
            const uint32_t vrow = (uint32_t)((kf * 16 + (lane & 15)) * 272);
#pragma unroll
            for (int nf = 0; nf < 17; ++nf) {
                uint32_t vh2[2], vl2[2];
                ldsm_x2t(vh2, vsH + vrow + (uint32_t)(nf * 16));
                ldsm_x2t(vl2, vsL + vrow + (uint32_t)(nf * 16));
                mma_f16(O[nf], Ph, vh2);
                mma_f16(O[nf], Ph, vl2);
            }
        }
        __syncthreads();
        load_vtile(jn);
    }
    const float i0 = 1.f / l0, i1 = 1.f / l1;
    float ss0 = 0.f, ss1 = 0.f;
#pragma unroll
    for (int nf = 0; nf < 17; ++nf) {
        O[nf][0] *= i0; O[nf][1] *= i0; O[nf][2] *= i1; O[nf][3] *= i1;
        ss0 += O[nf][0] * O[nf][0] + O[nf][1] * O[nf][1];
        ss1 += O[nf][2] * O[nf][2] + O[nf][3] * O[nf][3];
    }
    ss0 += __shfl_xor_sync(~0u, ss0, 1); ss0 += __shfl_xor_sync(~0u, ss0, 2);
    ss1 += __shfl_xor_sync(~0u, ss1, 1); ss1 += __shfl_xor_sync(~0u, ss1, 2);
    const float t0 = __shfl_sync(~0u, O[0][0], lane & ~3);
    const float t1 = __shfl_sync(~0u, O[0][2], lane & ~3);
    const float d0 = rsqrtf(fmaxf(fabsf(2.f * t0 * t0 - ss0), 1e-8f));
    const float d1 = rsqrtf(fmaxf(fabsf(2.f * t1 * t1 - ss1), 1e-8f));
    const int hh = bh & 15;
    const long long tok0 = (long long)(bh >> 4) * 1024 + iq * 128 + w * 16 + (lane >> 2);
    const long long o0 = tok0 * KCT + hh * 129, o1 = (tok0 + 8) * KCT + hh * 129;
#pragma unroll
    for (int nf = 0; nf < 17; ++nf) {
        const int cc = nf * 8 + (lane & 3) * 2;
        if (cc < 129) {
            ch[o0 + cc] = __float2half_rn(O[nf][0] * d0);
            ch[o1 + cc] = __float2half_rn(O[nf][2] * d1);
        }
        if (cc + 1 < 129) {
            ch[o0 + cc + 1] = __float2half_rn(O[nf][1] * d0);
            ch[o1 + cc + 1] = __float2half_rn(O[nf][3] * d1);
        }
    }
}

// ---------- unified convert (all fp32->fp16 jobs + biascat in ONE launch) ----------
__global__ void __launch_bounds__(256)
convert_all(const float* __restrict__ x, const float* __restrict__ wq,
            const float* __restrict__ wkva, const float* __restrict__ wkvb,
            const float* __restrict__ wo,
            const float* __restrict__ wq_b, const float* __restrict__ wkva_b,
            __half* __restrict__ xh, __half* __restrict__ wqkva,
            __half* __restrict__ wkvbh, __half* __restrict__ woh,
            float* __restrict__ biasqa)
{
    const int base = blockIdx.x * 1024 + threadIdx.x;
#pragma unroll
    for (int t = 0; t < 4; ++t) {
        const int idx = base + t * 256;
        if (idx < E0) {
            ((uint2*)xh)[idx] = pack4(((const float4*)x)[idx]);
        } else if (idx < E1) {
            const int i = idx - E0;
            ((uint2*)wqkva)[i] = pack4(((const float4*)wq)[i]);
        } else if (idx < E2) {
            const int i = idx - E1;
            ((uint2*)(wqkva + (size_t)3072 * 2048))[i] = pack4(((const float4*)wkva)[i]);
        } else if (idx < E3) {
            const int i = idx - E2;
            const int r = i / 129, c = i % 129;
            if (c < 128) {
                const float* p = wkvb + (long long)r * 513 + c * 4;
                float4 v;
                v.x = p[0]; v.y = p[1]; v.z = p[2]; v.w = p[3];
                *(uint2*)(wkvbh + (long long)r * KVN + c * 4) = pack4(v);
            } else {
                wkvbh[(long long)r * KVN + 512] = __float2half_rn(wkvb[(long long)r * 513 + 512]);
            }
        } else if (idx < E4) {
            const int i = idx - E3;
            const int r = i / 516, c = i % 516;
            const float4 v = *(const float4*)(wo + (long long)r * 2064 + c * 4);
            *(uint2*)(woh + (long long)r * KCT + c * 4) = pack4(v);
        } else if (idx < E5) {
            const int i = idx - E4;
            float4 v;
            if (i < 768)      v = ((const float4*)wq_b)[i];
            else if (i < 912) v = ((const float4*)wkva_b)[i - 768];
            else              v = make_float4(0.f, 0.f, 0.f, 0.f);
            ((float4*)biasqa)[i] = v;
        }
    }
}

__global__ void __launch_bounds__(256)
rmsnorm_kpe_kernel(const __half* __restrict__ qkva, const float* __restrict__ w,
                   const float* __restrict__ fc, const float* __restrict__ fs,
                   __half* __restrict__ kvnh, float* __restrict__ kpe)
{
    const int tok = blockIdx.x, s = tok & (S_ - 1), tid = threadIdx.x;
    const __half* in = qkva + (size_t)tok * NQA + 3072;
    __shared__ float sp[512];
    __shared__ float sh[8];
    float local = 0.f;
    for (int i = tid; i < 512; i += 256) { float v = __half2float(in[i]); local += v * v; }
    float r = rsqrtf(block_sum_256(local, sh) * (1.0f / 512.f) + 1e-6f);
    float l2 = 0.f;
    for (int i = tid; i < 512; i += 256) {
        float v = __half2float(in[i]) * r * w[i];
        sp[i] = v;
        l2 += v * v;
    }
    float tot2 = block_sum_256(l2, sh);
    const long long ob = (long long)tok * KVN;
    if (tid == 0) kvnh[ob] = __float2half_rn(sqrtf(tot2 + 1.f));
    for (int i = tid; i < 512; i += 256) kvnh[ob + 1 + i] = __float2half_rn(sp[i]);
    if (tid < 32) {
        float x1 = __half2float(in[512 + 2 * tid]), x2 = __half2float(in[512 + 2 * tid + 1]);
        float c = fc[s * 32 + tid], sn = fs[s * 32 + tid];
        kpe[(size_t)tok * 64 + 2 * tid]     = x1 * c - x2 * sn;
        kpe[(size_t)tok * 64 + 2 * tid + 1] = x1 * sn + x2 * c;
    }
}

__global__ void __launch_bounds__(256)
post_q_kernel(const __half* __restrict__ qkva, const float* __restrict__ fc,
              const float* __restrict__ fs,
              __half* __restrict__ qshp, float* __restrict__ tq)
{
    const int gw = (blockIdx.x * blockDim.x + threadIdx.x) >> 5, lane = threadIdx.x & 31;
    if (gw >= M_ * H_) return;
    const int h = gw % H_, tok = gw / H_, b = tok / S_, s = tok & (S_ - 1);
    const __half* qr = qkva + (size_t)tok * NQA + h * 192;
    const uint2 q4 = *(const uint2*)(qr + lane * 4);
    const __half2 qa = *(const __half2*)(&q4.x), qb = *(const __half2*)(&q4.y);
    const float2 fa = __half22float2(qa), fb = __half22float2(qb);
    const float c = fc[s * 32 + lane], sn = fs[s * 32 + lane];
    const __half2 rp = *(const __half2*)(qr + 128 + 2 * lane);
    const float2 rr = __half22float2(rp);
    const float r0 = rr.x * c - rr.y * sn, r1 = rr.x * sn + rr.y * c;
    float ss = r0 * r0 + r1 * r1 + fa.x * fa.x + fa.y * fa.y + fb.x * fb.x + fb.y * fb.y;
    ss = warp_sum(ss);
    const long long row = ((long long)b * H_ + h) * S_ + s;
    if (lane == 0) tq[row] = sqrtf(ss + 1.f);
    const long long ob = row * KQS;
    *(uint2*)(qshp + ob + lane * 4) = q4;                      // spatial copy (already fp16)
    *(__half2*)(qshp + ob + 128 + 2 * lane) = __floats2half2_rn(r0, r1);
}

__global__ void __launch_bounds__(256)
post_kv_kernel(const float* __restrict__ kv2, const float* __restrict__ kpe,
               __half* __restrict__ kshp, float* __restrict__ tk,
               __half* __restrict__ vhp, __half* __restrict__ vlp)
{
    const int gw = (blockIdx.x * blockDim.x + threadIdx.x) >> 5, lane = threadIdx.x & 31;
    if (gw >= M_ * H_) return;
    const int h = gw % H_, tok = gw / H_, b = tok / S_, s = tok & (S_ - 1);
    const float* row = kv2 + ((size_t)tok * H_ + h) * 256;
    const float* pe = kpe + (size_t)tok * 64;
    const float4 kn = *(const float4*)(row + lane * 4);
    const float2 pp = *(const float2*)(pe + lane * 2);
    float ss = kn.x * kn.x + kn.y * kn.y + kn.z * kn.z + kn.w * kn.w + pp.x * pp.x + pp.y * pp.y;
    ss = warp_sum(ss);
    const long long krow = ((long long)b * H_ + h) * S_ + s;
    if (lane == 0) tk[krow] = sqrtf(ss + 1.f);
    const long long kb = krow * KQS;
    *(uint2*)(kshp + kb + lane * 4) = pack4(kn);
    *(__half2*)(kshp + kb + 128 + 2 * lane) = __floats2half2_rn(pp.x, pp.y);
    const float4 vv = *(const float4*)(row + 128 + lane * 4);
    float sv = vv.x * vv.x + vv.y * vv.y + vv.z * vv.z + vv.w * vv.w;
    sv = warp_sum(sv);
    const long long vb = ((long long)b * H_ + h) * S_ * VDIM + (long long)s * VDIM;
    if (lane == 0) hsplit(sqrtf(sv + 1.f), vhp, vlp, vb);
    hsplit(vv.x, vhp, vlp, vb + 1 + lane * 4);
    hsplit(vv.y, vhp, vlp, vb + 2 + lane * 4);
    hsplit(vv.z, vhp, vlp, vb + 3 + lane * 4);
    hsplit(vv.w, vhp, vlp, vb + 4 + lane * 4);
}

__global__ void __launch_bounds__(256)
final_t_kernel(float* __restrict__ out)
{
    const int row = blockIdx.x, tid = threadIdx.x;
    float* p = out + (size_t)row * 2048;
    __shared__ float sh[8];
    float local = 0.f;
    for (int i = 1 + tid; i < 2048; i += 256) { float v = p[i]; local += v * v; }
    float tot = block_sum_256(local, sh);
    if (tid == 0) p[0] = sqrtf(tot + 1.f);
}

extern "C" void kernel_launch(void* const* d_in, const int* in_sizes, int n_in,
                              void* d_out, int out_size)
{
    (void)in_sizes; (void)n_in; (void)out_size;
    const float* x      = (const float*)d_in[0];
    const float* fc     = (const float*)d_in[1];
    const float* fs     = (const float*)d_in[2];
    const float* wq_w   = (const float*)d_in[4];
    const float* wq_b   = (const float*)d_in[5];
    const float* wkva_w = (const float*)d_in[6];
    const float* wkva_b = (const float*)d_in[7];
    const float* kvnw   = (const float*)d_in[8];
    const float* wkvb_w = (const float*)d_in[9];
    const float* wkvb_b = (const float*)d_in[10];
    const float* wo_w   = (const float*)d_in[11];
    const float* wo_b   = (const float*)d_in[12];
    float* out = (float*)d_out;

    float *kpe, *kv2, *tq, *tk, *biasqa;
    cudaGetSymbolAddress((void**)&kpe, g_kpe);
    cudaGetSymbolAddress((void**)&kv2, g_kv2);
    cudaGetSymbolAddress((void**)&tq, g_tq);
    cudaGetSymbolAddress((void**)&tk, g_tk);
    cudaGetSymbolAddress((void**)&biasqa, g_biasqa);
    __half *qkvah, *xh, *wqkva, *kvnh, *wkvbh, *ch, *woh, *qsh, *ksh, *vth, *vtl;
    cudaGetSymbolAddress((void**)&qkvah, g_qkvah);
    cudaGetSymbolAddress((void**)&xh, g_xh);
    cudaGetSymbolAddress((void**)&wqkva, g_wqkva);
    cudaGetSymbolAddress((void**)&kvnh, g_kvnh);
    cudaGetSymbolAddress((void**)&wkvbh, g_wkvbh);
    cudaGetSymbolAddress((void**)&ch, g_ch);
    cudaGetSymbolAddress((void**)&woh, g_woh);
    cudaGetSymbolAddress((void**)&qsh, g_qsh);
    cudaGetSymbolAddress((void**)&ksh, g_ksh);
    cudaGetSymbolAddress((void**)&vth, g_vth);
    cudaGetSymbolAddress((void**)&vtl, g_vtl);

    cudaFuncSetAttribute(gemm_h1<__half>, cudaFuncAttributeMaxDynamicSharedMemorySize, (int)DSMEM_H);
    cudaFuncSetAttribute(gemm_h1<float>, cudaFuncAttributeMaxDynamicSharedMemorySize, (int)DSMEM_H);
    cudaFuncSetAttribute(fused_attn, cudaFuncAttributeMaxDynamicSharedMemorySize, (int)DSMEM_F);

    const dim3 blk(256);
    convert_all<<<(E5 + 1023) / 1024, blk>>>(x, wq_w, wkva_w, wkvb_w, wo_w,
                                             wq_b, wkva_b,
                                             xh, wqkva, wkvbh, woh, biasqa);

    // fused Q + KV-A projection -> fp16: (4096x2048) @ (3712x2048)^T
    gemm_h1<__half><<<dim3(29, 32), blk, DSMEM_H>>>(xh, 2048, wqkva, 2048,
                                                    qkvah, NQA, biasqa, 3648, 2048);
    rmsnorm_kpe_kernel<<<M_, blk>>>(qkvah, kvnw, fc, fs, kvnh, kpe);
    // KV-B proj -> fp32 (V needs 2-term split downstream)
    gemm_h1<float><<<dim3(32, 32), blk, DSMEM_H>>>(kvnh, KVN, wkvbh, KVN,
                                                   kv2, 4096, wkvb_b, 4096, KVN);
    post_q_kernel<<<(M_ * H_) / 8, blk>>>(qkvah, fc, fs, qsh, tq);
    post_kv_kernel<<<(M_ * H_) / 8, blk>>>(kv2, kpe, ksh, tk, vth, vtl);
    fused_attn<<<dim3(8, 64), blk, DSMEM_F>>>(qsh, ksh, tq, tk, vth, vtl, ch);
    // out proj: (4096x2112) @ (2047x2112)^T -> out[:,1:]
    gemm_h1<float><<<dim3(16, 32), blk, DSMEM_H>>>(ch, KCT, woh, KCT,
                                                   out + 1, 2048, wo_b, 2047, KCT);
    final_t_kernel<<<M_, blk>>>(out);
}